// round 2
// baseline (speedup 1.0000x reference)
#include <cuda_runtime.h>
#include <math.h>

#define DIM   128
#define D2    256
#define NI    65536
#define NC    8192
#define EI    524288
#define EC    65536
#define TT    102400
#define SS    2048
#define VV    100000
#define NCAT  1000

// ---------------- scratch (device globals; no allocation allowed) -------------
__device__ float g_item_agg[NI * DIM];   // 32 MB
__device__ float g_cat_agg [NC * DIM];   //  4 MB
__device__ float g_et      [NI * DIM];   // 32 MB
__device__ float g_ft      [NC * DIM];   //  4 MB
__device__ float g_eft     [TT * D2];    // 100 MB
__device__ float g_U       [TT * D2];    // 100 MB
__device__ float g_lastE   [SS * D2];
__device__ float g_Vs      [SS * D2];
__device__ float g_alpha   [TT];
__device__ float g_sg      [SS * D2];
__device__ float g_B       [SS * NCAT];
__device__ int   g_start   [SS];
__device__ int   g_last    [SS];

// ---------------- init ----------------
__global__ void k_init() {
    int i = blockIdx.x * blockDim.x + threadIdx.x;
    if (i < NI * DIM) g_item_agg[i] = 0.f;
    if (i < NC * DIM) g_cat_agg[i]  = 0.f;
    if (i < SS) { g_start[i] = -1; g_last[i] = 0; }
}

// ---------------- edge scatter: agg[dst] += w * table[nodemap[src]] ----------
__global__ void k_edges(const int* __restrict__ edges, const float* __restrict__ ew,
                        const int* __restrict__ nodemap, const float* __restrict__ table,
                        float* __restrict__ agg, int E) {
    long gid = (long)blockIdx.x * blockDim.x + threadIdx.x;
    if (gid >= (long)E * 32) return;
    int e    = (int)(gid >> 5);
    int lane = (int)(gid & 31);
    int src = edges[e];
    int dst = edges[E + e];
    float w = ew[e];
    int id = nodemap[src];
    float4 v = *(const float4*)(table + (size_t)id * DIM + lane * 4);
    float* o = agg + (size_t)dst * DIM + lane * 4;
    asm volatile("red.global.add.v4.f32 [%0], {%1,%2,%3,%4};"
                 :: "l"(o), "f"(v.x * w), "f"(v.y * w), "f"(v.z * w), "f"(v.w * w)
                 : "memory");
}

// ---------------- generic SGEMM: C[M,N] = A[M,K](lda) @ B[N,K]^T (+bias) -----
// mode 2: also add Bcat[row*NCAT + c4i[col]] (final output epilogue)
// Requirements: M % 128 == 0, K % 8 == 0. N arbitrary (guarded).
__global__ __launch_bounds__(256) void k_sgemm(
    float* __restrict__ C, const float* __restrict__ A, int lda,
    const float* __restrict__ B, int M, int N, int K,
    const float* __restrict__ bias, int mode,
    const float* __restrict__ Bcat, const int* __restrict__ c4i) {
    __shared__ float As[8][128];
    __shared__ float Bs[8][128];
    const int tid = threadIdx.x;
    const int bm = blockIdx.y * 128;
    const int bn = blockIdx.x * 128;
    const int tx = tid & 15;
    const int ty = tid >> 4;
    float acc[8][8];
#pragma unroll
    for (int i = 0; i < 8; i++)
#pragma unroll
        for (int j = 0; j < 8; j++) acc[i][j] = 0.f;

    const int lrow = tid >> 1;
    const int lk   = (tid & 1) * 4;
    const float* Ap = A + (size_t)(bm + lrow) * lda + lk;
    const bool  bok = (bn + lrow) < N;
    const float* Bp = B + (size_t)(bn + lrow) * K + lk;

    for (int k0 = 0; k0 < K; k0 += 8) {
        float4 av = *(const float4*)(Ap + k0);
        float4 bv = bok ? *(const float4*)(Bp + k0) : make_float4(0.f, 0.f, 0.f, 0.f);
        __syncthreads();
        As[lk + 0][lrow] = av.x; As[lk + 1][lrow] = av.y;
        As[lk + 2][lrow] = av.z; As[lk + 3][lrow] = av.w;
        Bs[lk + 0][lrow] = bv.x; Bs[lk + 1][lrow] = bv.y;
        Bs[lk + 2][lrow] = bv.z; Bs[lk + 3][lrow] = bv.w;
        __syncthreads();
#pragma unroll
        for (int kk = 0; kk < 8; kk++) {
            float a[8], b[8];
            *(float4*)&a[0] = *(const float4*)&As[kk][ty * 8];
            *(float4*)&a[4] = *(const float4*)&As[kk][ty * 8 + 4];
            *(float4*)&b[0] = *(const float4*)&Bs[kk][tx * 8];
            *(float4*)&b[4] = *(const float4*)&Bs[kk][tx * 8 + 4];
#pragma unroll
            for (int i = 0; i < 8; i++)
#pragma unroll
                for (int j = 0; j < 8; j++) acc[i][j] += a[i] * b[j];
        }
    }
#pragma unroll
    for (int i = 0; i < 8; i++) {
        const int row = bm + ty * 8 + i;
#pragma unroll
        for (int j = 0; j < 8; j++) {
            const int col = bn + tx * 8 + j;
            if (col < N) {
                float v = acc[i][j];
                if (bias) v += bias[col];
                if (mode == 2) v += Bcat[(size_t)row * NCAT + c4i[col]];
                C[(size_t)row * N + col] = v;
            }
        }
    }
}

// ---------------- session boundaries (segment_ids is sorted) ----------------
__global__ void k_bounds(const int* __restrict__ seg) {
    int t = blockIdx.x * blockDim.x + threadIdx.x;
    if (t >= TT) return;
    int s = seg[t];
    if (t == TT - 1 || seg[t + 1] != s) g_last[s]  = t;
    if (t == 0      || seg[t - 1] != s) g_start[s] = t;
}

// ---------------- eft[t] = [et[item2idx[t]] | ft[cat2idx[t]]] ---------------
__global__ void k_build_eft(const int* __restrict__ i2x, const int* __restrict__ c2x,
                            const float* __restrict__ et, const float* __restrict__ ft,
                            float* __restrict__ eft) {
    long gid = (long)blockIdx.x * blockDim.x + threadIdx.x;
    if (gid >= (long)TT * 64) return;
    int t = (int)(gid >> 6);
    int q = (int)(gid & 63);
    float4 v;
    if (q < 32) v = *(const float4*)(et + (size_t)i2x[t] * DIM + q * 4);
    else        v = *(const float4*)(ft + (size_t)c2x[t] * DIM + (q - 32) * 4);
    *(float4*)(eft + (size_t)t * D2 + q * 4) = v;
}

// ---------------- lastE[s] = eft[last[s]] -----------------------------------
__global__ void k_lastE(const float* __restrict__ eft, float* __restrict__ lastE) {
    int gid = blockIdx.x * blockDim.x + threadIdx.x;
    if (gid >= SS * 64) return;
    int s = gid >> 6;
    int q = gid & 63;
    int t = g_last[s];
    *(float4*)(lastE + (size_t)s * D2 + q * 4) =
        *(const float4*)(eft + (size_t)t * D2 + q * 4);
}

// ---------------- alpha[t] = q . sigmoid(U[t] + Vs[seg[t]]) + q_b -----------
__global__ void k_alpha(const float* __restrict__ U, const float* __restrict__ Vs,
                        const int* __restrict__ seg, const float* __restrict__ qW,
                        const float* __restrict__ qb, float* __restrict__ alpha) {
    long gid = (long)blockIdx.x * blockDim.x + threadIdx.x;
    int t = (int)(gid >> 5);
    int lane = (int)(gid & 31);
    if (t >= TT) return;
    int s = seg[t];
    const float* u = U  + (size_t)t * D2;
    const float* v = Vs + (size_t)s * D2;
    float sum = 0.f;
#pragma unroll
    for (int i = lane; i < D2; i += 32) {
        float h = u[i] + v[i];
        float sg = 1.f / (1.f + expf(-h));
        sum += qW[i] * sg;
    }
#pragma unroll
    for (int o = 16; o; o >>= 1) sum += __shfl_xor_sync(0xFFFFFFFFu, sum, o);
    if (lane == 0) alpha[t] = sum + qb[0];
}

// ---------------- sg[s] = sum_t alpha[t]*eft[t] over session s --------------
__global__ void k_sg(const float* __restrict__ eft, const float* __restrict__ alpha,
                     float* __restrict__ sg) {
    int s = blockIdx.x;
    int d = threadIdx.x;  // 256
    float acc = 0.f;
    int st = g_start[s];
    if (st >= 0) {
        int en = g_last[s];
        for (int t = st; t <= en; ++t)
            acc += alpha[t] * eft[(size_t)t * D2 + d];
    }
    sg[(size_t)s * D2 + d] = acc;
}

// ============================ host launcher =================================
extern "C" void kernel_launch(void* const* d_in, const int* in_sizes, int n_in,
                              void* d_out, int out_size) {
    const int*   items    = (const int*)  d_in[0];
    const int*   cats     = (const int*)  d_in[1];
    const int*   item2idx = (const int*)  d_in[2];
    const int*   cat2idx  = (const int*)  d_in[3];
    const int*   item_e   = (const int*)  d_in[4];
    const int*   cat_e    = (const int*)  d_in[5];
    const float* item_ew  = (const float*)d_in[6];
    const float* cat_ew   = (const float*)d_in[7];
    const int*   seg      = (const int*)  d_in[8];
    const int*   cat4item = (const int*)  d_in[9];
    const float* item_tab = (const float*)d_in[10];
    const float* cat_tab  = (const float*)d_in[11];
    const float* iW  = (const float*)d_in[12];
    const float* ib  = (const float*)d_in[13];
    const float* cW  = (const float*)d_in[14];
    const float* cb  = (const float*)d_in[15];
    const float* w1W = (const float*)d_in[16];
    const float* w1b = (const float*)d_in[17];
    const float* w2W = (const float*)d_in[18];
    const float* qW  = (const float*)d_in[19];
    const float* qb  = (const float*)d_in[20];
    float* out = (float*)d_out;

    static float *p_iagg = nullptr, *p_cagg, *p_et, *p_ft, *p_eft, *p_U,
                 *p_lastE, *p_Vs, *p_alpha, *p_sg, *p_B;
    if (!p_iagg) {
        cudaGetSymbolAddress((void**)&p_iagg,  g_item_agg);
        cudaGetSymbolAddress((void**)&p_cagg,  g_cat_agg);
        cudaGetSymbolAddress((void**)&p_et,    g_et);
        cudaGetSymbolAddress((void**)&p_ft,    g_ft);
        cudaGetSymbolAddress((void**)&p_eft,   g_eft);
        cudaGetSymbolAddress((void**)&p_U,     g_U);
        cudaGetSymbolAddress((void**)&p_lastE, g_lastE);
        cudaGetSymbolAddress((void**)&p_Vs,    g_Vs);
        cudaGetSymbolAddress((void**)&p_alpha, g_alpha);
        cudaGetSymbolAddress((void**)&p_sg,    g_sg);
        cudaGetSymbolAddress((void**)&p_B,     g_B);
    }

    // 1. init scratch
    k_init<<<(NI * DIM + 255) / 256, 256>>>();

    // 2. edge scatters
    k_edges<<<(EI * 32) / 256, 256>>>(item_e, item_ew, items, item_tab, p_iagg, EI);
    k_edges<<<(EC * 32) / 256, 256>>>(cat_e,  cat_ew,  cats,  cat_tab,  p_cagg, EC);

    // 3. node linear transforms: et = agg @ W^T + b
    { dim3 g(1, NI / 128); k_sgemm<<<g, 256>>>(p_et, p_iagg, DIM, iW, NI, DIM, DIM, ib, 0, nullptr, nullptr); }
    { dim3 g(1, NC / 128); k_sgemm<<<g, 256>>>(p_ft, p_cagg, DIM, cW, NC, DIM, DIM, cb, 0, nullptr, nullptr); }

    // 4. session bounds + eft gather + last-embedding gather
    k_bounds<<<TT / 256, 256>>>(seg);
    k_build_eft<<<(TT * 64) / 256, 256>>>(item2idx, cat2idx, p_et, p_ft, p_eft);
    k_lastE<<<(SS * 64) / 256, 256>>>(p_eft, p_lastE);

    // 5. attention pre-activations: U = eft @ w1^T + w1_b ; Vs = lastE @ w2^T
    { dim3 g(2, TT / 128); k_sgemm<<<g, 256>>>(p_U,  p_eft,   D2, w1W, TT, D2, D2, w1b,    0, nullptr, nullptr); }
    { dim3 g(2, SS / 128); k_sgemm<<<g, 256>>>(p_Vs, p_lastE, D2, w2W, SS, D2, D2, nullptr, 0, nullptr, nullptr); }

    // 6. alpha + session aggregation
    k_alpha<<<(TT * 32) / 256, 256>>>(p_U, p_Vs, seg, qW, qb, p_alpha);
    k_sg<<<SS, 256>>>(p_eft, p_alpha, p_sg);

    // 7. B = sg[:,128:] @ cat_tab^T   [S, NCAT]
    { dim3 g((NCAT + 127) / 128, SS / 128);
      k_sgemm<<<g, 256>>>(p_B, p_sg + DIM, D2, cat_tab, SS, NCAT, DIM, nullptr, 0, nullptr, nullptr); }

    // 8. out = sg[:,:128] @ item_tab^T + B[:, cat4item]   [S, V]
    { dim3 g((VV + 127) / 128, SS / 128);
      k_sgemm<<<g, 256>>>(out, p_sg, D2, item_tab, SS, VV, DIM, nullptr, 2, p_B, cat4item); }
}

// round 5
// speedup vs baseline: 1.1965x; 1.1965x over previous
#include <cuda_runtime.h>
#include <math.h>

#define DIM   128
#define D2    256
#define NI    65536
#define NC    8192
#define EI    524288
#define EC    65536
#define TT    102400
#define SS    2048
#define VV    100000
#define NCAT  1000

// ---------------- scratch (device globals; no allocation allowed) -------------
__device__ float g_item_agg[NI * DIM];
__device__ float g_cat_agg [NC * DIM];
__device__ float g_et      [NI * DIM];
__device__ float g_ft      [NC * DIM];
__device__ float g_eft     [TT * D2];
__device__ float g_U       [TT * D2];
__device__ float g_lastE   [SS * D2];
__device__ float g_Vs      [SS * D2];
__device__ float g_alpha   [TT];
__device__ float g_sg      [SS * D2];
__device__ float g_B       [SS * NCAT];
__device__ int   g_start   [SS];
__device__ int   g_last    [SS];

// ---------------- init ----------------
__global__ void k_init() {
    int i = blockIdx.x * blockDim.x + threadIdx.x;
    if (i < NI * DIM) g_item_agg[i] = 0.f;
    if (i < NC * DIM) g_cat_agg[i]  = 0.f;
    if (i < SS) { g_start[i] = -1; g_last[i] = 0; }
}

// ---------------- edge scatter ----------------
__global__ void k_edges(const int* __restrict__ edges, const float* __restrict__ ew,
                        const int* __restrict__ nodemap, const float* __restrict__ table,
                        float* __restrict__ agg, int E) {
    long gid = (long)blockIdx.x * blockDim.x + threadIdx.x;
    if (gid >= (long)E * 32) return;
    int e    = (int)(gid >> 5);
    int lane = (int)(gid & 31);
    int src = edges[e];
    int dst = edges[E + e];
    float w = ew[e];
    int id = nodemap[src];
    float4 v = *(const float4*)(table + (size_t)id * DIM + lane * 4);
    float* o = agg + (size_t)dst * DIM + lane * 4;
    asm volatile("red.global.add.v4.f32 [%0], {%1,%2,%3,%4};"
                 :: "l"(o), "f"(v.x * w), "f"(v.y * w), "f"(v.z * w), "f"(v.w * w)
                 : "memory");
}

// ---------------- tf32 helpers ----------------
__device__ __forceinline__ unsigned f2tf32(float x) {
    unsigned u;
    asm("cvt.rna.tf32.f32 %0, %1;" : "=r"(u) : "f"(x));
    return u;
}
__device__ __forceinline__ void mma_tf32(float c[4], const unsigned a[4], const unsigned b[2]) {
    asm volatile(
        "mma.sync.aligned.m16n8k8.row.col.f32.tf32.tf32.f32 "
        "{%0,%1,%2,%3}, {%4,%5,%6,%7}, {%8,%9}, {%0,%1,%2,%3};"
        : "+f"(c[0]), "+f"(c[1]), "+f"(c[2]), "+f"(c[3])
        : "r"(a[0]), "r"(a[1]), "r"(a[2]), "r"(a[3]), "r"(b[0]), "r"(b[1]));
}

// ---------------- tensor-core GEMM: C[M,N] = A[M,K](lda) @ B[N,K]^T (+bias) --
// PRECISE=1: hi/lo split (3 MMA chains) for ~fp32 accuracy, BK=16.
// PRECISE=0: single-pass tf32, BK=32.
// mode 2: also add Bcat[row*NCAT + c4i[col]].
// Requirements: M%128==0, K%BK==0, lda = A row stride. N arbitrary.
template<int PRECISE, int BK>
__global__ __launch_bounds__(256) void k_tgemm(
    float* __restrict__ C, const float* __restrict__ A, int lda,
    const float* __restrict__ B, int M, int N, int K,
    const float* __restrict__ bias, int mode,
    const float* __restrict__ Bcat, const int* __restrict__ c4i) {
    constexpr int CH  = BK / 4;          // float4 chunks per row
    constexpr int NLD = CH / 2;          // float4 loads per thread per tile
    __shared__ unsigned Ah[CH * 128 * 4];
    __shared__ unsigned Bh[CH * 128 * 4];
    __shared__ unsigned Al[PRECISE ? CH * 128 * 4 : 1];
    __shared__ unsigned Bl[PRECISE ? CH * 128 * 4 : 1];

    const int tid  = threadIdx.x;
    const int lane = tid & 31;
    const int warp = tid >> 5;
    const int wm = (warp >> 1) * 32;     // warp m-offset (4 warps in m)
    const int wn = (warp & 1) * 64;      // warp n-offset (2 warps in n)
    const int tg = lane & 3;
    const int gp = lane >> 2;
    const int bm = blockIdx.y * 128;
    const int bn = blockIdx.x * 128;

    float acc[2][8][4];
#pragma unroll
    for (int mt = 0; mt < 2; mt++)
#pragma unroll
        for (int nt = 0; nt < 8; nt++)
#pragma unroll
            for (int e = 0; e < 4; e++) acc[mt][nt][e] = 0.f;

    for (int k0 = 0; k0 < K; k0 += BK) {
        float4 va[NLD], vb[NLD];
#pragma unroll
        for (int i = 0; i < NLD; i++) {
            int idx = i * 256 + tid;
            int m = idx / CH, c = idx % CH;
            va[i] = *(const float4*)(A + (size_t)(bm + m) * lda + k0 + c * 4);
            vb[i] = (bn + m) < N
                  ? *(const float4*)(B + (size_t)(bn + m) * K + k0 + c * 4)
                  : make_float4(0.f, 0.f, 0.f, 0.f);
        }
        __syncthreads();
#pragma unroll
        for (int i = 0; i < NLD; i++) {
            int idx = i * 256 + tid;
            int m = idx / CH, c = idx % CH;
            int base = (c * 128 + m) * 4;
            const float* pa = (const float*)&va[i];
            const float* pb = (const float*)&vb[i];
#pragma unroll
            for (int e = 0; e < 4; e++) {
                unsigned h = f2tf32(pa[e]);
                Ah[base + e] = h;
                if (PRECISE) Al[base + e] = f2tf32(pa[e] - __uint_as_float(h));
                h = f2tf32(pb[e]);
                Bh[base + e] = h;
                if (PRECISE) Bl[base + e] = f2tf32(pb[e] - __uint_as_float(h));
            }
        }
        __syncthreads();
#pragma unroll
        for (int kk = 0; kk < BK / 8; kk++) {
            const int c0i = kk * 2, c1i = kk * 2 + 1;
            unsigned a_h[2][4], b_h[8][2];
            unsigned a_l[PRECISE ? 2 : 1][4], b_l[PRECISE ? 8 : 1][2];
#pragma unroll
            for (int mt = 0; mt < 2; mt++) {
                int r = wm + mt * 16 + gp;
                a_h[mt][0] = Ah[(c0i * 128 + r) * 4 + tg];
                a_h[mt][1] = Ah[(c0i * 128 + r + 8) * 4 + tg];
                a_h[mt][2] = Ah[(c1i * 128 + r) * 4 + tg];
                a_h[mt][3] = Ah[(c1i * 128 + r + 8) * 4 + tg];
                if (PRECISE) {
                    a_l[mt][0] = Al[(c0i * 128 + r) * 4 + tg];
                    a_l[mt][1] = Al[(c0i * 128 + r + 8) * 4 + tg];
                    a_l[mt][2] = Al[(c1i * 128 + r) * 4 + tg];
                    a_l[mt][3] = Al[(c1i * 128 + r + 8) * 4 + tg];
                }
            }
#pragma unroll
            for (int nt = 0; nt < 8; nt++) {
                int n = wn + nt * 8 + gp;
                b_h[nt][0] = Bh[(c0i * 128 + n) * 4 + tg];
                b_h[nt][1] = Bh[(c1i * 128 + n) * 4 + tg];
                if (PRECISE) {
                    b_l[nt][0] = Bl[(c0i * 128 + n) * 4 + tg];
                    b_l[nt][1] = Bl[(c1i * 128 + n) * 4 + tg];
                }
            }
#pragma unroll
            for (int mt = 0; mt < 2; mt++)
#pragma unroll
                for (int nt = 0; nt < 8; nt++) {
                    mma_tf32(acc[mt][nt], a_h[mt], b_h[nt]);
                    if (PRECISE) {
                        mma_tf32(acc[mt][nt], a_h[mt], b_l[nt]);
                        mma_tf32(acc[mt][nt], a_l[mt], b_h[nt]);
                    }
                }
        }
        __syncthreads();
    }

    // epilogue
#pragma unroll
    for (int mt = 0; mt < 2; mt++) {
        int row0 = bm + wm + mt * 16 + gp;
#pragma unroll
        for (int nt = 0; nt < 8; nt++) {
            int col = bn + wn + nt * 8 + 2 * tg;
            int g0 = -1, g1 = -1;
            if (mode == 2) {
                if (col < N)     g0 = c4i[col];
                if (col + 1 < N) g1 = c4i[col + 1];
            }
#pragma unroll
            for (int half = 0; half < 2; half++) {
                int row = row0 + half * 8;
                float* crow = C + (size_t)row * N;
#pragma unroll
                for (int e = 0; e < 2; e++) {
                    int cc = col + e;
                    if (cc < N) {
                        float v = acc[mt][nt][half * 2 + e];
                        if (bias) v += bias[cc];
                        if (mode == 2) v += Bcat[(size_t)row * NCAT + (e ? g1 : g0)];
                        crow[cc] = v;
                    }
                }
            }
        }
    }
}

// ---------------- session boundaries ----------------
__global__ void k_bounds(const int* __restrict__ seg) {
    int t = blockIdx.x * blockDim.x + threadIdx.x;
    if (t >= TT) return;
    int s = seg[t];
    if (t == TT - 1 || seg[t + 1] != s) g_last[s]  = t;
    if (t == 0      || seg[t - 1] != s) g_start[s] = t;
}

// ---------------- eft build ----------------
__global__ void k_build_eft(const int* __restrict__ i2x, const int* __restrict__ c2x,
                            const float* __restrict__ et, const float* __restrict__ ft,
                            float* __restrict__ eft) {
    long gid = (long)blockIdx.x * blockDim.x + threadIdx.x;
    if (gid >= (long)TT * 64) return;
    int t = (int)(gid >> 6);
    int q = (int)(gid & 63);
    float4 v;
    if (q < 32) v = *(const float4*)(et + (size_t)i2x[t] * DIM + q * 4);
    else        v = *(const float4*)(ft + (size_t)c2x[t] * DIM + (q - 32) * 4);
    *(float4*)(eft + (size_t)t * D2 + q * 4) = v;
}

// ---------------- last-embedding gather ----------------
__global__ void k_lastE(const float* __restrict__ eft, float* __restrict__ lastE) {
    int gid = blockIdx.x * blockDim.x + threadIdx.x;
    if (gid >= SS * 64) return;
    int s = gid >> 6;
    int q = gid & 63;
    int t = g_last[s];
    *(float4*)(lastE + (size_t)s * D2 + q * 4) =
        *(const float4*)(eft + (size_t)t * D2 + q * 4);
}

// ---------------- alpha ----------------
__global__ void k_alpha(const float* __restrict__ U, const float* __restrict__ Vs,
                        const int* __restrict__ seg, const float* __restrict__ qW,
                        const float* __restrict__ qb, float* __restrict__ alpha) {
    long gid = (long)blockIdx.x * blockDim.x + threadIdx.x;
    int t = (int)(gid >> 5);
    int lane = (int)(gid & 31);
    if (t >= TT) return;
    int s = seg[t];
    const float* u = U  + (size_t)t * D2;
    const float* v = Vs + (size_t)s * D2;
    float sum = 0.f;
#pragma unroll
    for (int i = lane; i < D2; i += 32) {
        float h = u[i] + v[i];
        float sg = 1.f / (1.f + expf(-h));
        sum += qW[i] * sg;
    }
#pragma unroll
    for (int o = 16; o; o >>= 1) sum += __shfl_xor_sync(0xFFFFFFFFu, sum, o);
    if (lane == 0) alpha[t] = sum + qb[0];
}

// ---------------- session aggregation ----------------
__global__ void k_sg(const float* __restrict__ eft, const float* __restrict__ alpha,
                     float* __restrict__ sg) {
    int s = blockIdx.x;
    int d = threadIdx.x;  // 256
    float acc = 0.f;
    int st = g_start[s];
    if (st >= 0) {
        int en = g_last[s];
        for (int t = st; t <= en; ++t)
            acc += alpha[t] * eft[(size_t)t * D2 + d];
    }
    sg[(size_t)s * D2 + d] = acc;
}

// ============================ host launcher =================================
extern "C" void kernel_launch(void* const* d_in, const int* in_sizes, int n_in,
                              void* d_out, int out_size) {
    const int*   items    = (const int*)  d_in[0];
    const int*   cats     = (const int*)  d_in[1];
    const int*   item2idx = (const int*)  d_in[2];
    const int*   cat2idx  = (const int*)  d_in[3];
    const int*   item_e   = (const int*)  d_in[4];
    const int*   cat_e    = (const int*)  d_in[5];
    const float* item_ew  = (const float*)d_in[6];
    const float* cat_ew   = (const float*)d_in[7];
    const int*   seg      = (const int*)  d_in[8];
    const int*   cat4item = (const int*)  d_in[9];
    const float* item_tab = (const float*)d_in[10];
    const float* cat_tab  = (const float*)d_in[11];
    const float* iW  = (const float*)d_in[12];
    const float* ib  = (const float*)d_in[13];
    const float* cW  = (const float*)d_in[14];
    const float* cb  = (const float*)d_in[15];
    const float* w1W = (const float*)d_in[16];
    const float* w1b = (const float*)d_in[17];
    const float* w2W = (const float*)d_in[18];
    const float* qW  = (const float*)d_in[19];
    const float* qb  = (const float*)d_in[20];
    float* out = (float*)d_out;

    static float *p_iagg = nullptr, *p_cagg, *p_et, *p_ft, *p_eft, *p_U,
                 *p_lastE, *p_Vs, *p_alpha, *p_sg, *p_B;
    if (!p_iagg) {
        cudaGetSymbolAddress((void**)&p_iagg,  g_item_agg);
        cudaGetSymbolAddress((void**)&p_cagg,  g_cat_agg);
        cudaGetSymbolAddress((void**)&p_et,    g_et);
        cudaGetSymbolAddress((void**)&p_ft,    g_ft);
        cudaGetSymbolAddress((void**)&p_eft,   g_eft);
        cudaGetSymbolAddress((void**)&p_U,     g_U);
        cudaGetSymbolAddress((void**)&p_lastE, g_lastE);
        cudaGetSymbolAddress((void**)&p_Vs,    g_Vs);
        cudaGetSymbolAddress((void**)&p_alpha, g_alpha);
        cudaGetSymbolAddress((void**)&p_sg,    g_sg);
        cudaGetSymbolAddress((void**)&p_B,     g_B);
    }

    // 1. init scratch
    k_init<<<(NI * DIM + 255) / 256, 256>>>();

    // 2. edge scatters
    k_edges<<<(EI * 32) / 256, 256>>>(item_e, item_ew, items, item_tab, p_iagg, EI);
    k_edges<<<(EC * 32) / 256, 256>>>(cat_e,  cat_ew,  cats,  cat_tab,  p_cagg, EC);

    // 3. node linear transforms (precise tf32)
    { dim3 g(1, NI / 128); k_tgemm<1,16><<<g, 256>>>(p_et, p_iagg, DIM, iW, NI, DIM, DIM, ib, 0, nullptr, nullptr); }
    { dim3 g(1, NC / 128); k_tgemm<1,16><<<g, 256>>>(p_ft, p_cagg, DIM, cW, NC, DIM, DIM, cb, 0, nullptr, nullptr); }

    // 4. session bounds + eft gather + last-embedding gather
    k_bounds<<<TT / 256, 256>>>(seg);
    k_build_eft<<<(TT * 64) / 256, 256>>>(item2idx, cat2idx, p_et, p_ft, p_eft);
    k_lastE<<<(SS * 64) / 256, 256>>>(p_eft, p_lastE);

    // 5. attention pre-activations (precise tf32)
    { dim3 g(2, TT / 128); k_tgemm<1,16><<<g, 256>>>(p_U,  p_eft,   D2, w1W, TT, D2, D2, w1b,    0, nullptr, nullptr); }
    { dim3 g(2, SS / 128); k_tgemm<1,16><<<g, 256>>>(p_Vs, p_lastE, D2, w2W, SS, D2, D2, nullptr, 0, nullptr, nullptr); }

    // 6. alpha + session aggregation
    k_alpha<<<(TT * 32) / 256, 256>>>(p_U, p_Vs, seg, qW, qb, p_alpha);
    k_sg<<<SS, 256>>>(p_eft, p_alpha, p_sg);

    // 7. B = sg[:,128:] @ cat_tab^T   [S, NCAT]  (fast tf32)
    { dim3 g((NCAT + 127) / 128, SS / 128);
      k_tgemm<0,32><<<g, 256>>>(p_B, p_sg + DIM, D2, cat_tab, SS, NCAT, DIM, nullptr, 0, nullptr, nullptr); }

    // 8. out = sg[:,:128] @ item_tab^T + B[:, cat4item]   [S, V]  (fast tf32)
    { dim3 g((VV + 127) / 128, SS / 128);
      k_tgemm<0,32><<<g, 256>>>(out, p_sg, D2, item_tab, SS, VV, DIM, nullptr, 2, p_B, cat4item); }
}

// round 8
// speedup vs baseline: 1.5375x; 1.2849x over previous
#include <cuda_runtime.h>
#include <stdint.h>
#include <math.h>

#define DIM   128
#define D2    256
#define NI    65536
#define NC    8192
#define EI    524288
#define EC    65536
#define TT    102400
#define SS    2048
#define VV    100000
#define NCAT  1000

// ---------------- scratch (device globals; no allocation allowed) -------------
__device__ float g_item_agg[NI * DIM];
__device__ float g_cat_agg [NC * DIM];
__device__ float g_et      [NI * DIM];
__device__ float g_ft      [NC * DIM];
__device__ float g_Uet     [NI * D2];
__device__ float g_Uft     [NC * D2];
__device__ float g_lastE   [SS * D2];
__device__ float g_Vs      [SS * D2];
__device__ float g_alpha   [TT];
__device__ float g_sg      [SS * D2];
__device__ float g_B       [SS * NCAT];
__device__ int   g_start   [SS];
__device__ int   g_last    [SS];

// ---------------- init ----------------
__global__ void k_init() {
    int i = blockIdx.x * blockDim.x + threadIdx.x;
    if (i < NI * DIM) g_item_agg[i] = 0.f;
    if (i < NC * DIM) g_cat_agg[i]  = 0.f;
    if (i < SS) { g_start[i] = -1; g_last[i] = 0; }
}

// ---------------- edge scatter ----------------
__global__ void k_edges(const int* __restrict__ edges, const float* __restrict__ ew,
                        const int* __restrict__ nodemap, const float* __restrict__ table,
                        float* __restrict__ agg, int E) {
    long gid = (long)blockIdx.x * blockDim.x + threadIdx.x;
    if (gid >= (long)E * 32) return;
    int e    = (int)(gid >> 5);
    int lane = (int)(gid & 31);
    int src = edges[e];
    int dst = edges[E + e];
    float w = ew[e];
    int id = nodemap[src];
    float4 v = *(const float4*)(table + (size_t)id * DIM + lane * 4);
    float* o = agg + (size_t)dst * DIM + lane * 4;
    asm volatile("red.global.add.v4.f32 [%0], {%1,%2,%3,%4};"
                 :: "l"(o), "f"(v.x * w), "f"(v.y * w), "f"(v.z * w), "f"(v.w * w)
                 : "memory");
}

// ---------------- tf32 helpers ----------------
__device__ __forceinline__ unsigned f2tf32(float x) {
    unsigned u;
    asm("cvt.rna.tf32.f32 %0, %1;" : "=r"(u) : "f"(x));
    return u;
}
__device__ __forceinline__ void mma_tf32(float c[4], const unsigned a[4], const unsigned b[2]) {
    asm volatile(
        "mma.sync.aligned.m16n8k8.row.col.f32.tf32.tf32.f32 "
        "{%0,%1,%2,%3}, {%4,%5,%6,%7}, {%8,%9}, {%0,%1,%2,%3};"
        : "+f"(c[0]), "+f"(c[1]), "+f"(c[2]), "+f"(c[3])
        : "r"(a[0]), "r"(a[1]), "r"(a[2]), "r"(a[3]), "r"(b[0]), "r"(b[1]));
}

// ============ pipelined tensor GEMM: C[M,N] = A[M,K](lda) @ B[N,K]^T(ldb) ====
// PRECISE=1: hi/lo tf32 split (3 MMA chains), BK=16. PRECISE=0: single tf32, BK=32.
// mode 2: also add Bcat[row*NCAT + c4i[col]]. Dynamic smem = 2*2*BK*128*4 bytes.
// M%128==0, K%BK==0; N arbitrary. cp.async 2-stage double-buffered.
template<int PRECISE, int BK>
__global__ __launch_bounds__(256, PRECISE ? 1 : 2) void k_pgemm(
    float* __restrict__ C, const float* __restrict__ A, int lda,
    const float* __restrict__ B, int ldb, int M, int N, int K,
    const float* __restrict__ bias, int mode,
    const float* __restrict__ Bcat, const int* __restrict__ c4i) {
    constexpr int CH   = BK / 4;            // 16B chunks per row
    constexpr int TILE = BK * 128;          // floats per tile
    constexpr int NPT  = (CH * 128) / 256;  // chunks per thread per tile
    extern __shared__ float sm[];

    const int tid  = threadIdx.x;
    const int lane = tid & 31;
    const int warp = tid >> 5;
    const int wm = (warp >> 1) * 32;
    const int wn = (warp & 1) * 64;
    const int tg = lane & 3;
    const int gp = lane >> 2;
    const int bm = blockIdx.y * 128;
    const int bn = blockIdx.x * 128;
    const uint32_t sbase = (uint32_t)__cvta_generic_to_shared(sm);

    float acc[2][8][4];
#pragma unroll
    for (int mt = 0; mt < 2; mt++)
#pragma unroll
        for (int nt = 0; nt < 8; nt++)
#pragma unroll
            for (int e = 0; e < 4; e++) acc[mt][nt][e] = 0.f;

    const int nIter = K / BK;

#define LOAD_STAGE(stage, k0)                                                          \
    {                                                                                  \
        const int off_ = (stage) * 2 * TILE;                                           \
        _Pragma("unroll")                                                              \
        for (int i_ = 0; i_ < NPT; i_++) {                                             \
            int idx_ = i_ * 256 + tid;                                                 \
            int m_ = idx_ / CH, c_ = idx_ % CH;                                        \
            const float* sa_ = A + (size_t)(bm + m_) * lda + (k0) + c_ * 4;            \
            asm volatile("cp.async.cg.shared.global [%0], [%1], 16;"                   \
                         :: "r"(sbase + (unsigned)(off_ + (c_ * 128 + m_) * 4) * 4u),  \
                            "l"(sa_));                                                 \
            int br_ = bn + m_;                                                         \
            const float* sb_ = B + (size_t)(br_ < N ? br_ : 0) * ldb + (k0) + c_ * 4;  \
            int p_ = (br_ < N) ? 16 : 0;                                               \
            asm volatile("cp.async.cg.shared.global [%0], [%1], 16, %2;"               \
                         :: "r"(sbase + (unsigned)(off_ + TILE + (c_ * 128 + m_) * 4) * 4u), \
                            "l"(sb_), "r"(p_));                                        \
        }                                                                              \
        asm volatile("cp.async.commit_group;");                                       \
    }

    LOAD_STAGE(0, 0)
    if (nIter > 1) { LOAD_STAGE(1, BK) }
    else           { asm volatile("cp.async.commit_group;"); }

    for (int it = 0; it < nIter; ++it) {
        asm volatile("cp.async.wait_group 1;");
        __syncthreads();
        const float* smA = sm + (it & 1) * 2 * TILE;
        const float* smB = smA + TILE;
#pragma unroll
        for (int kk = 0; kk < BK / 8; kk++) {
            const int c0 = kk * 2, c1 = kk * 2 + 1;
            unsigned a_h[2][4], b_h[8][2];
            unsigned a_l[PRECISE ? 2 : 1][4], b_l[PRECISE ? 8 : 1][2];
#pragma unroll
            for (int mt = 0; mt < 2; mt++) {
                int r = wm + mt * 16 + gp;
                float f0 = smA[(c0 * 128 + r)     * 4 + tg];
                float f1 = smA[(c0 * 128 + r + 8) * 4 + tg];
                float f2 = smA[(c1 * 128 + r)     * 4 + tg];
                float f3 = smA[(c1 * 128 + r + 8) * 4 + tg];
                a_h[mt][0] = f2tf32(f0); a_h[mt][1] = f2tf32(f1);
                a_h[mt][2] = f2tf32(f2); a_h[mt][3] = f2tf32(f3);
                if (PRECISE) {
                    a_l[mt][0] = f2tf32(f0 - __uint_as_float(a_h[mt][0]));
                    a_l[mt][1] = f2tf32(f1 - __uint_as_float(a_h[mt][1]));
                    a_l[mt][2] = f2tf32(f2 - __uint_as_float(a_h[mt][2]));
                    a_l[mt][3] = f2tf32(f3 - __uint_as_float(a_h[mt][3]));
                }
            }
#pragma unroll
            for (int nt = 0; nt < 8; nt++) {
                int n = wn + nt * 8 + gp;
                float f0 = smB[(c0 * 128 + n) * 4 + tg];
                float f1 = smB[(c1 * 128 + n) * 4 + tg];
                b_h[nt][0] = f2tf32(f0); b_h[nt][1] = f2tf32(f1);
                if (PRECISE) {
                    b_l[nt][0] = f2tf32(f0 - __uint_as_float(b_h[nt][0]));
                    b_l[nt][1] = f2tf32(f1 - __uint_as_float(b_h[nt][1]));
                }
            }
#pragma unroll
            for (int mt = 0; mt < 2; mt++)
#pragma unroll
                for (int nt = 0; nt < 8; nt++) {
                    mma_tf32(acc[mt][nt], a_h[mt], b_h[nt]);
                    if (PRECISE) {
                        mma_tf32(acc[mt][nt], a_h[mt], b_l[nt]);
                        mma_tf32(acc[mt][nt], a_l[mt], b_h[nt]);
                    }
                }
        }
        __syncthreads();
        if (it + 2 < nIter) { LOAD_STAGE(it & 1, (it + 2) * BK) }
        else                { asm volatile("cp.async.commit_group;"); }
    }
#undef LOAD_STAGE

    // epilogue
#pragma unroll
    for (int mt = 0; mt < 2; mt++) {
        int row0 = bm + wm + mt * 16 + gp;
#pragma unroll
        for (int nt = 0; nt < 8; nt++) {
            int col = bn + wn + nt * 8 + 2 * tg;
            int g0 = 0, g1 = 0;
            if (mode == 2) {
                if (col < N)     g0 = c4i[col];
                if (col + 1 < N) g1 = c4i[col + 1];
            }
#pragma unroll
            for (int half = 0; half < 2; half++) {
                int row = row0 + half * 8;
                float* crow = C + (size_t)row * N;
#pragma unroll
                for (int e = 0; e < 2; e++) {
                    int cc = col + e;
                    if (cc < N) {
                        float v = acc[mt][nt][half * 2 + e];
                        if (bias) v += bias[cc];
                        if (mode == 2) v += Bcat[(size_t)row * NCAT + (e ? g1 : g0)];
                        crow[cc] = v;
                    }
                }
            }
        }
    }
}

// ---------------- session boundaries ----------------
__global__ void k_bounds(const int* __restrict__ seg) {
    int t = blockIdx.x * blockDim.x + threadIdx.x;
    if (t >= TT) return;
    int s = seg[t];
    if (t == TT - 1 || seg[t + 1] != s) g_last[s]  = t;
    if (t == 0      || seg[t - 1] != s) g_start[s] = t;
}

// ---------------- lastE[s] = [et[i2x[last]], ft[c2x[last]]] -----------------
__global__ void k_lastE(const int* __restrict__ i2x, const int* __restrict__ c2x,
                        const float* __restrict__ et, const float* __restrict__ ft,
                        float* __restrict__ lastE) {
    int gid = blockIdx.x * blockDim.x + threadIdx.x;
    if (gid >= SS * 64) return;
    int s = gid >> 6;
    int q = gid & 63;
    int t = g_last[s];
    float4 v;
    if (q < 32) v = *(const float4*)(et + (size_t)i2x[t] * DIM + q * 4);
    else        v = *(const float4*)(ft + (size_t)c2x[t] * DIM + (q - 32) * 4);
    *(float4*)(lastE + (size_t)s * D2 + q * 4) = v;
}

// ------ alpha[t] = q . sigmoid(Uet[i2x[t]] + Uft[c2x[t]] + Vs[seg[t]]) + qb --
__global__ void k_alpha(const float* __restrict__ Uet, const float* __restrict__ Uft,
                        const float* __restrict__ Vs,
                        const int* __restrict__ i2x, const int* __restrict__ c2x,
                        const int* __restrict__ seg, const float* __restrict__ qW,
                        const float* __restrict__ qb, float* __restrict__ alpha) {
    long gid = (long)blockIdx.x * blockDim.x + threadIdx.x;
    int t = (int)(gid >> 5);
    int lane = (int)(gid & 31);
    if (t >= TT) return;
    const float* u  = Uet + (size_t)i2x[t] * D2;
    const float* u2 = Uft + (size_t)c2x[t] * D2;
    const float* v  = Vs  + (size_t)seg[t] * D2;
    float sum = 0.f;
#pragma unroll
    for (int i = lane; i < D2; i += 32) {
        float h = u[i] + u2[i] + v[i];
        float sg = 1.f / (1.f + expf(-h));
        sum += qW[i] * sg;
    }
#pragma unroll
    for (int o = 16; o; o >>= 1) sum += __shfl_xor_sync(0xFFFFFFFFu, sum, o);
    if (lane == 0) alpha[t] = sum + qb[0];
}

// ------ sg[s,d] = sum_t alpha[t] * ([et[i2x[t]] | ft[c2x[t]]])[d] -----------
__global__ void k_sg(const int* __restrict__ i2x, const int* __restrict__ c2x,
                     const float* __restrict__ et, const float* __restrict__ ft,
                     const float* __restrict__ alpha, float* __restrict__ sg) {
    int s = blockIdx.x;
    int d = threadIdx.x;  // 256
    float acc = 0.f;
    int st = g_start[s];
    if (st >= 0) {
        int en = g_last[s];
        if (d < 128) {
            for (int t = st; t <= en; ++t)
                acc += alpha[t] * et[(size_t)i2x[t] * DIM + d];
        } else {
            for (int t = st; t <= en; ++t)
                acc += alpha[t] * ft[(size_t)c2x[t] * DIM + (d - 128)];
        }
    }
    sg[(size_t)s * D2 + d] = acc;
}

// ============================ host launcher =================================
extern "C" void kernel_launch(void* const* d_in, const int* in_sizes, int n_in,
                              void* d_out, int out_size) {
    const int*   items    = (const int*)  d_in[0];
    const int*   cats     = (const int*)  d_in[1];
    const int*   item2idx = (const int*)  d_in[2];
    const int*   cat2idx  = (const int*)  d_in[3];
    const int*   item_e   = (const int*)  d_in[4];
    const int*   cat_e    = (const int*)  d_in[5];
    const float* item_ew  = (const float*)d_in[6];
    const float* cat_ew   = (const float*)d_in[7];
    const int*   seg      = (const int*)  d_in[8];
    const int*   cat4item = (const int*)  d_in[9];
    const float* item_tab = (const float*)d_in[10];
    const float* cat_tab  = (const float*)d_in[11];
    const float* iW  = (const float*)d_in[12];
    const float* ib  = (const float*)d_in[13];
    const float* cW  = (const float*)d_in[14];
    const float* cb  = (const float*)d_in[15];
    const float* w1W = (const float*)d_in[16];
    const float* w1b = (const float*)d_in[17];
    const float* w2W = (const float*)d_in[18];
    const float* qW  = (const float*)d_in[19];
    const float* qb  = (const float*)d_in[20];
    float* out = (float*)d_out;

    static float *p_iagg = nullptr, *p_cagg, *p_et, *p_ft, *p_Uet, *p_Uft,
                 *p_lastE, *p_Vs, *p_alpha, *p_sg, *p_B;
    if (!p_iagg) {
        cudaGetSymbolAddress((void**)&p_iagg,  g_item_agg);
        cudaGetSymbolAddress((void**)&p_cagg,  g_cat_agg);
        cudaGetSymbolAddress((void**)&p_et,    g_et);
        cudaGetSymbolAddress((void**)&p_ft,    g_ft);
        cudaGetSymbolAddress((void**)&p_Uet,   g_Uet);
        cudaGetSymbolAddress((void**)&p_Uft,   g_Uft);
        cudaGetSymbolAddress((void**)&p_lastE, g_lastE);
        cudaGetSymbolAddress((void**)&p_Vs,    g_Vs);
        cudaGetSymbolAddress((void**)&p_alpha, g_alpha);
        cudaGetSymbolAddress((void**)&p_sg,    g_sg);
        cudaGetSymbolAddress((void**)&p_B,     g_B);
        cudaFuncSetAttribute(k_pgemm<0,32>, cudaFuncAttributeMaxDynamicSharedMemorySize, 65536);
        cudaFuncSetAttribute(k_pgemm<1,16>, cudaFuncAttributeMaxDynamicSharedMemorySize, 32768);
    }
    const int SMF = 65536;   // fast: 2 stages * 2 tiles * 32*128 floats
    const int SMP = 32768;   // precise: 2 stages * 2 tiles * 16*128 floats

    // 1. init
    k_init<<<(NI * DIM + 255) / 256, 256>>>();

    // 2. edge scatters
    k_edges<<<(EI * 32) / 256, 256>>>(item_e, item_ew, items, item_tab, p_iagg, EI);
    k_edges<<<(EC * 32) / 256, 256>>>(cat_e,  cat_ew,  cats,  cat_tab,  p_cagg, EC);

    // 3. node GNN linears (precise): et = iagg @ iW^T + ib ; ft likewise
    { dim3 g(1, NI / 128); k_pgemm<1,16><<<g, 256, SMP>>>(p_et, p_iagg, DIM, iW, DIM, NI, DIM, DIM, ib, 0, nullptr, nullptr); }
    { dim3 g(1, NC / 128); k_pgemm<1,16><<<g, 256, SMP>>>(p_ft, p_cagg, DIM, cW, DIM, NC, DIM, DIM, cb, 0, nullptr, nullptr); }

    // 4. U factorization at node level (precise):
    //    Uet = et @ W1[:, :128]^T + w1b ;  Uft = ft @ W1[:, 128:]^T
    { dim3 g(2, NI / 128); k_pgemm<1,16><<<g, 256, SMP>>>(p_Uet, p_et, DIM, w1W,       D2, NI, D2, DIM, w1b,    0, nullptr, nullptr); }
    { dim3 g(2, NC / 128); k_pgemm<1,16><<<g, 256, SMP>>>(p_Uft, p_ft, DIM, w1W + DIM, D2, NC, D2, DIM, nullptr, 0, nullptr, nullptr); }

    // 5. session bounds + last embedding + Vs = lastE @ w2^T (precise)
    k_bounds<<<TT / 256, 256>>>(seg);
    k_lastE<<<(SS * 64) / 256, 256>>>(item2idx, cat2idx, p_et, p_ft, p_lastE);
    { dim3 g(2, SS / 128); k_pgemm<1,16><<<g, 256, SMP>>>(p_Vs, p_lastE, D2, w2W, D2, SS, D2, D2, nullptr, 0, nullptr, nullptr); }

    // 6. alpha (gather-add of Uet/Uft/Vs) + session aggregation
    k_alpha<<<(TT * 32) / 256, 256>>>(p_Uet, p_Uft, p_Vs, item2idx, cat2idx, seg, qW, qb, p_alpha);
    k_sg<<<SS, 256>>>(item2idx, cat2idx, p_et, p_ft, p_alpha, p_sg);

    // 7. B = sg[:,128:] @ cat_tab^T   [S, NCAT]  (fast)
    { dim3 g((NCAT + 127) / 128, SS / 128);
      k_pgemm<0,32><<<g, 256, SMF>>>(p_B, p_sg + DIM, D2, cat_tab, DIM, SS, NCAT, DIM, nullptr, 0, nullptr, nullptr); }

    // 8. out = sg[:,:128] @ item_tab^T + B[:, cat4item]   [S, V]  (fast)
    { dim3 g((VV + 127) / 128, SS / 128);
      k_pgemm<0,32><<<g, 256, SMF>>>(out, p_sg, D2, item_tab, DIM, SS, VV, DIM, nullptr, 2, p_B, cat4item); }
}

// round 10
// speedup vs baseline: 2.0007x; 1.3013x over previous
#include <cuda_runtime.h>
#include <cuda_fp16.h>
#include <stdint.h>
#include <math.h>

#define DIM   128
#define D2    256
#define NI    65536
#define NC    8192
#define EI    524288
#define EC    65536
#define TT    102400
#define SS    2048
#define VV    100000
#define NCAT  1000

// ---------------- scratch (device globals; no allocation allowed) -------------
__device__ float g_item_agg[NI * DIM];
__device__ float g_cat_agg [NC * DIM];
__device__ float g_et      [NI * DIM];
__device__ float g_ft      [NC * DIM];
__device__ float g_Uet     [NI * D2];
__device__ float g_Uft     [NC * D2];
__device__ float g_Vs      [SS * D2];
__device__ float g_alpha   [TT];
__device__ float g_B       [SS * NCAT];
__device__ int   g_start   [SS];
__device__ int   g_last    [SS];
// half operands
__device__ __half g_iaggh[NI * DIM], g_iaggl[NI * DIM];
__device__ __half g_caggh[NC * DIM], g_caggl[NC * DIM];
__device__ __half g_eth  [NI * DIM], g_etl  [NI * DIM];
__device__ __half g_fth  [NC * DIM], g_ftl  [NC * DIM];
__device__ __half g_lastEh[SS * D2], g_lastEl[SS * D2];
__device__ __half g_sgh  [SS * D2];
__device__ __half g_ith  [VV * DIM];
__device__ __half g_cth  [NCAT * DIM];
__device__ __half g_iWh  [DIM * DIM], g_cWh[DIM * DIM];
__device__ __half g_w1Wh [D2 * D2],   g_w2Wh[D2 * D2];

// ---------------- init ----------------
__global__ void k_init() {
    int i = blockIdx.x * blockDim.x + threadIdx.x;
    if (i < NI * DIM) g_item_agg[i] = 0.f;
    if (i < NC * DIM) g_cat_agg[i]  = 0.f;
    if (i < SS) { g_start[i] = -1; g_last[i] = 0; }
}

// ---------------- conversions ----------------
__global__ void k_cvt1h(const float* __restrict__ src, __half* __restrict__ dst, int n) {
    int i = blockIdx.x * blockDim.x + threadIdx.x;
    if (i < n) dst[i] = __float2half(src[i]);
}
__global__ void k_split2h(const float* __restrict__ src, __half* __restrict__ h,
                          __half* __restrict__ l, int n) {
    int i = blockIdx.x * blockDim.x + threadIdx.x;
    if (i >= n) return;
    float x = src[i];
    __half hh = __float2half(x);
    h[i] = hh;
    l[i] = __float2half(x - __half2float(hh));
}

// ---------------- edge scatter ----------------
__global__ void k_edges(const int* __restrict__ edges, const float* __restrict__ ew,
                        const int* __restrict__ nodemap, const float* __restrict__ table,
                        float* __restrict__ agg, int E) {
    long gid = (long)blockIdx.x * blockDim.x + threadIdx.x;
    if (gid >= (long)E * 32) return;
    int e    = (int)(gid >> 5);
    int lane = (int)(gid & 31);
    int src = edges[e];
    int dst = edges[E + e];
    float w = ew[e];
    int id = nodemap[src];
    float4 v = *(const float4*)(table + (size_t)id * DIM + lane * 4);
    float* o = agg + (size_t)dst * DIM + lane * 4;
    asm volatile("red.global.add.v4.f32 [%0], {%1,%2,%3,%4};"
                 :: "l"(o), "f"(v.x * w), "f"(v.y * w), "f"(v.z * w), "f"(v.w * w)
                 : "memory");
}

// ---------------- fp16 mma helper ----------------
__device__ __forceinline__ void mma_f16(float c[4], const unsigned a[4], const unsigned b[2]) {
    asm volatile(
        "mma.sync.aligned.m16n8k16.row.col.f32.f16.f16.f32 "
        "{%0,%1,%2,%3}, {%4,%5,%6,%7}, {%8,%9}, {%0,%1,%2,%3};"
        : "+f"(c[0]), "+f"(c[1]), "+f"(c[2]), "+f"(c[3])
        : "r"(a[0]), "r"(a[1]), "r"(a[2]), "r"(a[3]), "r"(b[0]), "r"(b[1]));
}

// ============ fp16 tensor GEMM: C[M,N] = A[M,K](lda) @ B[N,K]^T(ldb) =========
// SPLIT=1: A = Ah + Al (2 MMA chains, ~fp32-accurate A). SPLIT=0: single.
// mode 2: smem-staged coalesced epilogue with += Bcat[row*NCAT + c4i[col]].
// BK=32. M%128==0, K%32==0, N arbitrary. 2-stage cp.async double buffer.
// smem half2-word layout per tile: word(row, k2) at [row*PADW + k2], PADW=20.
#define PADW  20
#define TILEB (128 * PADW * 4)     // 10240 bytes per tile
template<int SPLIT>
__global__ __launch_bounds__(256, 2) void k_hgemm(
    float* __restrict__ C, const __half* __restrict__ Ah, const __half* __restrict__ Al,
    int lda, const __half* __restrict__ B, int ldb, int M, int N, int K,
    const float* __restrict__ bias, int mode,
    const float* __restrict__ Bcat, const int* __restrict__ c4i) {
    constexpr int NTILE  = SPLIT ? 3 : 2;
    constexpr int STAGEB = NTILE * TILEB;
    extern __shared__ char sm8[];

    const int tid  = threadIdx.x;
    const int lane = tid & 31;
    const int warp = tid >> 5;
    const int wm = (warp >> 1) * 32;
    const int wn = (warp & 1) * 64;
    const int tg = lane & 3;
    const int gp = lane >> 2;
    const int bm = blockIdx.y * 128;
    const int bn = blockIdx.x * 128;
    const uint32_t sbase = (uint32_t)__cvta_generic_to_shared(sm8);

    float acc[2][8][4];
#pragma unroll
    for (int mt = 0; mt < 2; mt++)
#pragma unroll
        for (int nt = 0; nt < 8; nt++)
#pragma unroll
            for (int e = 0; e < 4; e++) acc[mt][nt][e] = 0.f;

    const int nIter = K / 32;

    // each tile: 128 rows x 4 chunks of 16B (8 halves); 512 chunks, 2/thread
#define LOAD_STAGE(stage, k0)                                                           \
    {                                                                                   \
        const uint32_t so_ = sbase + (stage) * STAGEB;                                  \
        _Pragma("unroll")                                                               \
        for (int i_ = 0; i_ < 2; i_++) {                                                \
            int idx_ = i_ * 256 + tid;                                                  \
            int row_ = idx_ >> 2, c_ = idx_ & 3;                                        \
            uint32_t d_ = (uint32_t)(row_ * (PADW * 4) + c_ * 16);                      \
            const __half* pa_ = Ah + (size_t)(bm + row_) * lda + (k0) + c_ * 8;         \
            asm volatile("cp.async.cg.shared.global [%0], [%1], 16;"                    \
                         :: "r"(so_ + d_), "l"(pa_));                                   \
            if (SPLIT) {                                                                \
                const __half* pl_ = Al + (size_t)(bm + row_) * lda + (k0) + c_ * 8;     \
                asm volatile("cp.async.cg.shared.global [%0], [%1], 16;"                \
                             :: "r"(so_ + TILEB + d_), "l"(pl_));                       \
            }                                                                           \
            int rb_ = bn + row_; if (rb_ >= N) rb_ = N - 1;                             \
            const __half* pb_ = B + (size_t)rb_ * ldb + (k0) + c_ * 8;                  \
            asm volatile("cp.async.cg.shared.global [%0], [%1], 16;"                    \
                         :: "r"(so_ + (NTILE - 1) * TILEB + d_), "l"(pb_));             \
        }                                                                               \
        asm volatile("cp.async.commit_group;");                                        \
    }

    LOAD_STAGE(0, 0)
    if (nIter > 1) { LOAD_STAGE(1, 32) }
    else           { asm volatile("cp.async.commit_group;"); }

    for (int it = 0; it < nIter; ++it) {
        asm volatile("cp.async.wait_group 1;");
        __syncthreads();
        const uint32_t* wA = (const uint32_t*)(sm8 + (it & 1) * STAGEB);
        const uint32_t* wL = (const uint32_t*)(sm8 + (it & 1) * STAGEB + TILEB);
        const uint32_t* wB = (const uint32_t*)(sm8 + (it & 1) * STAGEB + (NTILE - 1) * TILEB);
#pragma unroll
        for (int kk = 0; kk < 2; kk++) {
            const int kb = kk * 8;
            unsigned a_h[2][4], b_h[8][2];
            unsigned a_l[SPLIT ? 2 : 1][4];
#pragma unroll
            for (int mt = 0; mt < 2; mt++) {
                int r = wm + mt * 16 + gp;
                a_h[mt][0] = wA[r * PADW + kb + tg];
                a_h[mt][1] = wA[(r + 8) * PADW + kb + tg];
                a_h[mt][2] = wA[r * PADW + kb + 4 + tg];
                a_h[mt][3] = wA[(r + 8) * PADW + kb + 4 + tg];
                if (SPLIT) {
                    a_l[mt][0] = wL[r * PADW + kb + tg];
                    a_l[mt][1] = wL[(r + 8) * PADW + kb + tg];
                    a_l[mt][2] = wL[r * PADW + kb + 4 + tg];
                    a_l[mt][3] = wL[(r + 8) * PADW + kb + 4 + tg];
                }
            }
#pragma unroll
            for (int nt = 0; nt < 8; nt++) {
                int n = wn + nt * 8 + gp;
                b_h[nt][0] = wB[n * PADW + kb + tg];
                b_h[nt][1] = wB[n * PADW + kb + 4 + tg];
            }
#pragma unroll
            for (int mt = 0; mt < 2; mt++)
#pragma unroll
                for (int nt = 0; nt < 8; nt++) {
                    mma_f16(acc[mt][nt], a_h[mt], b_h[nt]);
                    if (SPLIT) mma_f16(acc[mt][nt], a_l[mt], b_h[nt]);
                }
        }
        __syncthreads();
        if (it + 2 < nIter) { LOAD_STAGE(it & 1, (it + 2) * 32) }
        else                { asm volatile("cp.async.commit_group;"); }
    }
#undef LOAD_STAGE

    if (mode == 2) {
        // staged coalesced epilogue (N % 4 == 0 assumed for vector path)
        __syncthreads();
        float* so = (float*)sm8;   // 128 x 132 floats
#pragma unroll
        for (int mt = 0; mt < 2; mt++) {
            int r0 = wm + mt * 16 + gp;
#pragma unroll
            for (int nt = 0; nt < 8; nt++) {
                int cl = wn + nt * 8 + 2 * tg;
                so[r0 * 132 + cl]       = acc[mt][nt][0];
                so[r0 * 132 + cl + 1]   = acc[mt][nt][1];
                so[(r0 + 8) * 132 + cl]     = acc[mt][nt][2];
                so[(r0 + 8) * 132 + cl + 1] = acc[mt][nt][3];
            }
        }
        __syncthreads();
        int col = lane * 4;
        int cg = bn + col;
        if (cg < N) {
            int i0 = c4i[cg], i1 = c4i[cg + 1], i2 = c4i[cg + 2], i3 = c4i[cg + 3];
            for (int rr = warp; rr < 128; rr += 8) {
                int rg = bm + rr;
                const float* bc = Bcat + (size_t)rg * NCAT;
                float4 v = *(const float4*)&so[rr * 132 + col];
                v.x += bc[i0]; v.y += bc[i1]; v.z += bc[i2]; v.w += bc[i3];
                *(float4*)&C[(size_t)rg * N + cg] = v;
            }
        }
    } else {
#pragma unroll
        for (int mt = 0; mt < 2; mt++) {
            int row0 = bm + wm + mt * 16 + gp;
#pragma unroll
            for (int nt = 0; nt < 8; nt++) {
                int col = bn + wn + nt * 8 + 2 * tg;
#pragma unroll
                for (int half = 0; half < 2; half++) {
                    int row = row0 + half * 8;
                    float* crow = C + (size_t)row * N;
#pragma unroll
                    for (int e = 0; e < 2; e++) {
                        int cc = col + e;
                        if (cc < N) {
                            float v = acc[mt][nt][half * 2 + e];
                            if (bias) v += bias[cc];
                            crow[cc] = v;
                        }
                    }
                }
            }
        }
    }
}

// ---------------- session boundaries ----------------
__global__ void k_bounds(const int* __restrict__ seg) {
    int t = blockIdx.x * blockDim.x + threadIdx.x;
    if (t >= TT) return;
    int s = seg[t];
    if (t == TT - 1 || seg[t + 1] != s) g_last[s]  = t;
    if (t == 0      || seg[t - 1] != s) g_start[s] = t;
}

// ------- lastE (half hi/lo): [et[i2x[last]], ft[c2x[last]]] -----------------
__global__ void k_lastE(const int* __restrict__ i2x, const int* __restrict__ c2x,
                        const float* __restrict__ et, const float* __restrict__ ft,
                        __half* __restrict__ lh, __half* __restrict__ ll) {
    int gid = blockIdx.x * blockDim.x + threadIdx.x;
    if (gid >= SS * D2) return;
    int s = gid >> 8;
    int d = gid & 255;
    int t = g_last[s];
    float x = (d < 128) ? et[(size_t)i2x[t] * DIM + d]
                        : ft[(size_t)c2x[t] * DIM + (d - 128)];
    __half hh = __float2half(x);
    lh[gid] = hh;
    ll[gid] = __float2half(x - __half2float(hh));
}

// ------ alpha[t] = q . sigmoid(Uet[i2x[t]] + Uft[c2x[t]] + Vs[seg[t]]) + qb --
__global__ void k_alpha(const float* __restrict__ Uet, const float* __restrict__ Uft,
                        const float* __restrict__ Vs,
                        const int* __restrict__ i2x, const int* __restrict__ c2x,
                        const int* __restrict__ seg, const float* __restrict__ qW,
                        const float* __restrict__ qb, float* __restrict__ alpha) {
    long gid = (long)blockIdx.x * blockDim.x + threadIdx.x;
    int t = (int)(gid >> 5);
    int lane = (int)(gid & 31);
    if (t >= TT) return;
    const float* u  = Uet + (size_t)i2x[t] * D2;
    const float* u2 = Uft + (size_t)c2x[t] * D2;
    const float* v  = Vs  + (size_t)seg[t] * D2;
    float sum = 0.f;
#pragma unroll
    for (int i = lane; i < D2; i += 32) {
        float h = u[i] + u2[i] + v[i];
        float sg = 1.f / (1.f + expf(-h));
        sum += qW[i] * sg;
    }
#pragma unroll
    for (int o = 16; o; o >>= 1) sum += __shfl_xor_sync(0xFFFFFFFFu, sum, o);
    if (lane == 0) alpha[t] = sum + qb[0];
}

// ------ sg[s,d] (half) = sum_t alpha[t] * ([et[i2x[t]] | ft[c2x[t]]])[d] -----
__global__ void k_sg(const int* __restrict__ i2x, const int* __restrict__ c2x,
                     const float* __restrict__ et, const float* __restrict__ ft,
                     const float* __restrict__ alpha, __half* __restrict__ sgh) {
    int s = blockIdx.x;
    int d = threadIdx.x;  // 256
    float acc = 0.f;
    int st = g_start[s];
    if (st >= 0) {
        int en = g_last[s];
        if (d < 128) {
            for (int t = st; t <= en; ++t)
                acc += alpha[t] * et[(size_t)i2x[t] * DIM + d];
        } else {
            for (int t = st; t <= en; ++t)
                acc += alpha[t] * ft[(size_t)c2x[t] * DIM + (d - 128)];
        }
    }
    sgh[(size_t)s * D2 + d] = __float2half(acc);
}

// ============================ host launcher =================================
extern "C" void kernel_launch(void* const* d_in, const int* in_sizes, int n_in,
                              void* d_out, int out_size) {
    const int*   items    = (const int*)  d_in[0];
    const int*   cats     = (const int*)  d_in[1];
    const int*   item2idx = (const int*)  d_in[2];
    const int*   cat2idx  = (const int*)  d_in[3];
    const int*   item_e   = (const int*)  d_in[4];
    const int*   cat_e    = (const int*)  d_in[5];
    const float* item_ew  = (const float*)d_in[6];
    const float* cat_ew   = (const float*)d_in[7];
    const int*   seg      = (const int*)  d_in[8];
    const int*   cat4item = (const int*)  d_in[9];
    const float* item_tab = (const float*)d_in[10];
    const float* cat_tab  = (const float*)d_in[11];
    const float* iW  = (const float*)d_in[12];
    const float* ib  = (const float*)d_in[13];
    const float* cW  = (const float*)d_in[14];
    const float* cb  = (const float*)d_in[15];
    const float* w1W = (const float*)d_in[16];
    const float* w1b = (const float*)d_in[17];
    const float* w2W = (const float*)d_in[18];
    const float* qW  = (const float*)d_in[19];
    const float* qb  = (const float*)d_in[20];
    float* out = (float*)d_out;

    static float *p_iagg = nullptr, *p_cagg, *p_et, *p_ft, *p_Uet, *p_Uft,
                 *p_Vs, *p_alpha, *p_B;
    static __half *p_iaggh, *p_iaggl, *p_caggh, *p_caggl, *p_eth, *p_etl,
                  *p_fth, *p_ftl, *p_lEh, *p_lEl, *p_sgh, *p_ith, *p_cth,
                  *p_iWh, *p_cWh, *p_w1Wh, *p_w2Wh;
    if (!p_iagg) {
        cudaGetSymbolAddress((void**)&p_iagg,  g_item_agg);
        cudaGetSymbolAddress((void**)&p_cagg,  g_cat_agg);
        cudaGetSymbolAddress((void**)&p_et,    g_et);
        cudaGetSymbolAddress((void**)&p_ft,    g_ft);
        cudaGetSymbolAddress((void**)&p_Uet,   g_Uet);
        cudaGetSymbolAddress((void**)&p_Uft,   g_Uft);
        cudaGetSymbolAddress((void**)&p_Vs,    g_Vs);
        cudaGetSymbolAddress((void**)&p_alpha, g_alpha);
        cudaGetSymbolAddress((void**)&p_B,     g_B);
        cudaGetSymbolAddress((void**)&p_iaggh, g_iaggh);
        cudaGetSymbolAddress((void**)&p_iaggl, g_iaggl);
        cudaGetSymbolAddress((void**)&p_caggh, g_caggh);
        cudaGetSymbolAddress((void**)&p_caggl, g_caggl);
        cudaGetSymbolAddress((void**)&p_eth,   g_eth);
        cudaGetSymbolAddress((void**)&p_etl,   g_etl);
        cudaGetSymbolAddress((void**)&p_fth,   g_fth);
        cudaGetSymbolAddress((void**)&p_ftl,   g_ftl);
        cudaGetSymbolAddress((void**)&p_lEh,   g_lastEh);
        cudaGetSymbolAddress((void**)&p_lEl,   g_lastEl);
        cudaGetSymbolAddress((void**)&p_sgh,   g_sgh);
        cudaGetSymbolAddress((void**)&p_ith,   g_ith);
        cudaGetSymbolAddress((void**)&p_cth,   g_cth);
        cudaGetSymbolAddress((void**)&p_iWh,   g_iWh);
        cudaGetSymbolAddress((void**)&p_cWh,   g_cWh);
        cudaGetSymbolAddress((void**)&p_w1Wh,  g_w1Wh);
        cudaGetSymbolAddress((void**)&p_w2Wh,  g_w2Wh);
        cudaFuncSetAttribute(k_hgemm<0>, cudaFuncAttributeMaxDynamicSharedMemorySize, 69632);
        cudaFuncSetAttribute(k_hgemm<1>, cudaFuncAttributeMaxDynamicSharedMemorySize, 69632);
    }
    const int SMF = 69632;   // max(2*2*10240, 128*132*4=67584) rounded up
    const int SMP = 61440;   // 2 stages * 3 tiles * 10240

    // 1. init + static half conversions (weights + tables)
    k_init<<<(NI * DIM + 255) / 256, 256>>>();
    k_cvt1h<<<(VV * DIM + 255) / 256, 256>>>(item_tab, p_ith, VV * DIM);
    k_cvt1h<<<(NCAT * DIM + 255) / 256, 256>>>(cat_tab, p_cth, NCAT * DIM);
    k_cvt1h<<<(DIM * DIM + 255) / 256, 256>>>(iW,  p_iWh,  DIM * DIM);
    k_cvt1h<<<(DIM * DIM + 255) / 256, 256>>>(cW,  p_cWh,  DIM * DIM);
    k_cvt1h<<<(D2 * D2 + 255) / 256, 256>>>(w1W, p_w1Wh, D2 * D2);
    k_cvt1h<<<(D2 * D2 + 255) / 256, 256>>>(w2W, p_w2Wh, D2 * D2);

    // 2. edge scatters + split aggregates to half hi/lo
    k_edges<<<(EI * 32) / 256, 256>>>(item_e, item_ew, items, item_tab, p_iagg, EI);
    k_edges<<<(EC * 32) / 256, 256>>>(cat_e,  cat_ew,  cats,  cat_tab,  p_cagg, EC);
    k_split2h<<<(NI * DIM + 255) / 256, 256>>>(p_iagg, p_iaggh, p_iaggl, NI * DIM);
    k_split2h<<<(NC * DIM + 255) / 256, 256>>>(p_cagg, p_caggh, p_caggl, NC * DIM);

    // 3. node GNN linears (fp16 A-split): et = iagg @ iW^T + ib
    { dim3 g(1, NI / 128); k_hgemm<1><<<g, 256, SMP>>>(p_et, p_iaggh, p_iaggl, DIM, p_iWh, DIM, NI, DIM, DIM, ib, 0, nullptr, nullptr); }
    { dim3 g(1, NC / 128); k_hgemm<1><<<g, 256, SMP>>>(p_ft, p_caggh, p_caggl, DIM, p_cWh, DIM, NC, DIM, DIM, cb, 0, nullptr, nullptr); }
    k_split2h<<<(NI * DIM + 255) / 256, 256>>>(p_et, p_eth, p_etl, NI * DIM);
    k_split2h<<<(NC * DIM + 255) / 256, 256>>>(p_ft, p_fth, p_ftl, NC * DIM);

    // 4. U factorization at node level: Uet = et @ W1[:, :128]^T + w1b ; Uft likewise
    { dim3 g(2, NI / 128); k_hgemm<1><<<g, 256, SMP>>>(p_Uet, p_eth, p_etl, DIM, p_w1Wh,       D2, NI, D2, DIM, w1b,    0, nullptr, nullptr); }
    { dim3 g(2, NC / 128); k_hgemm<1><<<g, 256, SMP>>>(p_Uft, p_fth, p_ftl, DIM, p_w1Wh + DIM, D2, NC, D2, DIM, nullptr, 0, nullptr, nullptr); }

    // 5. session bounds + last embedding (half hi/lo) + Vs = lastE @ w2^T
    k_bounds<<<TT / 256, 256>>>(seg);
    k_lastE<<<(SS * D2 + 255) / 256, 256>>>(item2idx, cat2idx, p_et, p_ft, p_lEh, p_lEl);
    { dim3 g(2, SS / 128); k_hgemm<1><<<g, 256, SMP>>>(p_Vs, p_lEh, p_lEl, D2, p_w2Wh, D2, SS, D2, D2, nullptr, 0, nullptr, nullptr); }

    // 6. alpha + session aggregation (writes sg half)
    k_alpha<<<(TT * 32) / 256, 256>>>(p_Uet, p_Uft, p_Vs, item2idx, cat2idx, seg, qW, qb, p_alpha);
    k_sg<<<SS, 256>>>(item2idx, cat2idx, p_et, p_ft, p_alpha, p_sgh);

    // 7. B = sg[:,128:] @ cat_tab^T   [S, NCAT]
    { dim3 g((NCAT + 127) / 128, SS / 128);
      k_hgemm<0><<<g, 256, SMF>>>(p_B, p_sgh + DIM, nullptr, D2, p_cth, DIM, SS, NCAT, DIM, nullptr, 0, nullptr, nullptr); }

    // 8. out = sg[:,:128] @ item_tab^T + B[:, cat4item]   [S, V]
    { dim3 g((VV + 127) / 128, SS / 128);
      k_hgemm<0><<<g, 256, SMF>>>(out, p_sgh, nullptr, D2, p_ith, DIM, SS, VV, DIM, nullptr, 2, p_B, cat4item); }
}

// round 12
// speedup vs baseline: 3.3589x; 1.6789x over previous
#include <cuda_runtime.h>
#include <cuda_fp16.h>
#include <stdint.h>
#include <math.h>

#define DIM   128
#define D2    256
#define NI    65536
#define NC    8192
#define EI    524288
#define EC    65536
#define TT    102400
#define SS    2048
#define VV    100000
#define NCAT  1000

// ---------------- scratch (device globals; no allocation allowed) -------------
__device__ float g_item_agg[NI * DIM];
__device__ float g_cat_agg [NC * DIM];
__device__ float g_et      [NI * DIM];
__device__ float g_ft      [NC * DIM];
__device__ float g_Uet     [NI * D2];
__device__ float g_Uft     [NC * D2];
__device__ float g_Vs      [SS * D2];
__device__ float g_alpha   [TT];
__device__ int   g_start   [SS];
__device__ int   g_last    [SS];
// half operands
__device__ __half g_iaggh[NI * DIM], g_iaggl[NI * DIM];
__device__ __half g_caggh[NC * DIM], g_caggl[NC * DIM];
__device__ __half g_eth  [NI * DIM], g_etl  [NI * DIM];
__device__ __half g_fth  [NC * DIM], g_ftl  [NC * DIM];
__device__ __half g_lastEh[SS * D2], g_lastEl[SS * D2];
__device__ __half g_sgh  [SS * D2];
__device__ __half g_allh [VV * D2];          // fused [item_tab | cat_tab[c4i]] half
__device__ __half g_iWh  [DIM * DIM], g_cWh[DIM * DIM];
__device__ __half g_w1Wh [D2 * D2],   g_w2Wh[D2 * D2];

// ---------------- init ----------------
__global__ void k_init() {
    int i = blockIdx.x * blockDim.x + threadIdx.x;
    if (i < NI * DIM) g_item_agg[i] = 0.f;
    if (i < NC * DIM) g_cat_agg[i]  = 0.f;
    if (i < SS) { g_start[i] = -1; g_last[i] = 0; }
}

// ---------------- conversions ----------------
__global__ void k_cvt1h(const float* __restrict__ src, __half* __restrict__ dst, int n) {
    int i = blockIdx.x * blockDim.x + threadIdx.x;
    if (i < n) dst[i] = __float2half(src[i]);
}
__global__ void k_split2h(const float* __restrict__ src, __half* __restrict__ h,
                          __half* __restrict__ l, int n) {
    int i = blockIdx.x * blockDim.x + threadIdx.x;
    if (i >= n) return;
    float x = src[i];
    __half hh = __float2half(x);
    h[i] = hh;
    l[i] = __float2half(x - __half2float(hh));
}
// fused table: all[v, 0:128] = item_tab[v], all[v, 128:256] = cat_tab[c4i[v]]
__global__ void k_fuse(const float* __restrict__ it, const float* __restrict__ ct,
                       const int* __restrict__ c4i, __half* __restrict__ all) {
    int i = blockIdx.x * blockDim.x + threadIdx.x;
    if (i >= VV * D2) return;
    int v = i >> 8, d = i & 255;
    float x = (d < 128) ? it[(size_t)v * DIM + d]
                        : ct[(size_t)c4i[v] * DIM + (d - 128)];
    all[i] = __float2half(x);
}

// ---------------- edge scatter ----------------
__global__ void k_edges(const int* __restrict__ edges, const float* __restrict__ ew,
                        const int* __restrict__ nodemap, const float* __restrict__ table,
                        float* __restrict__ agg, int E) {
    long gid = (long)blockIdx.x * blockDim.x + threadIdx.x;
    if (gid >= (long)E * 32) return;
    int e    = (int)(gid >> 5);
    int lane = (int)(gid & 31);
    int src = edges[e];
    int dst = edges[E + e];
    float w = ew[e];
    int id = nodemap[src];
    float4 v = *(const float4*)(table + (size_t)id * DIM + lane * 4);
    float* o = agg + (size_t)dst * DIM + lane * 4;
    asm volatile("red.global.add.v4.f32 [%0], {%1,%2,%3,%4};"
                 :: "l"(o), "f"(v.x * w), "f"(v.y * w), "f"(v.z * w), "f"(v.w * w)
                 : "memory");
}

// ---------------- fp16 mma helper ----------------
__device__ __forceinline__ void mma_f16(float c[4], const unsigned a[4], const unsigned b[2]) {
    asm volatile(
        "mma.sync.aligned.m16n8k16.row.col.f32.f16.f16.f32 "
        "{%0,%1,%2,%3}, {%4,%5,%6,%7}, {%8,%9}, {%0,%1,%2,%3};"
        : "+f"(c[0]), "+f"(c[1]), "+f"(c[2]), "+f"(c[3])
        : "r"(a[0]), "r"(a[1]), "r"(a[2]), "r"(a[3]), "r"(b[0]), "r"(b[1]));
}

// ============ fp16 tensor GEMM: C[M,N] = A[M,K](lda) @ B[N,K]^T(ldb) =========
// SPLIT=1: A = Ah + Al (2 MMA chains). SPLIT=0: single.
// mode 0: direct store (+bias). mode 1: smem-staged coalesced float4 store.
// BK=32. M%128==0, K%32==0. 2-stage cp.async double buffer.
#define PADW  20
#define TILEB (128 * PADW * 4)
template<int SPLIT>
__global__ __launch_bounds__(256, 2) void k_hgemm(
    float* __restrict__ C, const __half* __restrict__ Ah, const __half* __restrict__ Al,
    int lda, const __half* __restrict__ B, int ldb, int M, int N, int K,
    const float* __restrict__ bias, int mode) {
    constexpr int NTILE  = SPLIT ? 3 : 2;
    constexpr int STAGEB = NTILE * TILEB;
    extern __shared__ char sm8[];

    const int tid  = threadIdx.x;
    const int lane = tid & 31;
    const int warp = tid >> 5;
    const int wm = (warp >> 1) * 32;
    const int wn = (warp & 1) * 64;
    const int tg = lane & 3;
    const int gp = lane >> 2;
    const int bm = blockIdx.y * 128;
    const int bn = blockIdx.x * 128;
    const uint32_t sbase = (uint32_t)__cvta_generic_to_shared(sm8);

    float acc[2][8][4];
#pragma unroll
    for (int mt = 0; mt < 2; mt++)
#pragma unroll
        for (int nt = 0; nt < 8; nt++)
#pragma unroll
            for (int e = 0; e < 4; e++) acc[mt][nt][e] = 0.f;

    const int nIter = K / 32;

#define LOAD_STAGE(stage, k0)                                                           \
    {                                                                                   \
        const uint32_t so_ = sbase + (stage) * STAGEB;                                  \
        _Pragma("unroll")                                                               \
        for (int i_ = 0; i_ < 2; i_++) {                                                \
            int idx_ = i_ * 256 + tid;                                                  \
            int row_ = idx_ >> 2, c_ = idx_ & 3;                                        \
            uint32_t d_ = (uint32_t)(row_ * (PADW * 4) + c_ * 16);                      \
            const __half* pa_ = Ah + (size_t)(bm + row_) * lda + (k0) + c_ * 8;         \
            asm volatile("cp.async.cg.shared.global [%0], [%1], 16;"                    \
                         :: "r"(so_ + d_), "l"(pa_));                                   \
            if (SPLIT) {                                                                \
                const __half* pl_ = Al + (size_t)(bm + row_) * lda + (k0) + c_ * 8;     \
                asm volatile("cp.async.cg.shared.global [%0], [%1], 16;"                \
                             :: "r"(so_ + TILEB + d_), "l"(pl_));                       \
            }                                                                           \
            int rb_ = bn + row_; if (rb_ >= N) rb_ = N - 1;                             \
            const __half* pb_ = B + (size_t)rb_ * ldb + (k0) + c_ * 8;                  \
            asm volatile("cp.async.cg.shared.global [%0], [%1], 16;"                    \
                         :: "r"(so_ + (NTILE - 1) * TILEB + d_), "l"(pb_));             \
        }                                                                               \
        asm volatile("cp.async.commit_group;");                                        \
    }

    LOAD_STAGE(0, 0)
    if (nIter > 1) { LOAD_STAGE(1, 32) }
    else           { asm volatile("cp.async.commit_group;"); }

    for (int it = 0; it < nIter; ++it) {
        asm volatile("cp.async.wait_group 1;");
        __syncthreads();
        const uint32_t* wA = (const uint32_t*)(sm8 + (it & 1) * STAGEB);
        const uint32_t* wL = (const uint32_t*)(sm8 + (it & 1) * STAGEB + TILEB);
        const uint32_t* wB = (const uint32_t*)(sm8 + (it & 1) * STAGEB + (NTILE - 1) * TILEB);
#pragma unroll
        for (int kk = 0; kk < 2; kk++) {
            const int kb = kk * 8;
            unsigned a_h[2][4], b_h[8][2];
            unsigned a_l[SPLIT ? 2 : 1][4];
#pragma unroll
            for (int mt = 0; mt < 2; mt++) {
                int r = wm + mt * 16 + gp;
                a_h[mt][0] = wA[r * PADW + kb + tg];
                a_h[mt][1] = wA[(r + 8) * PADW + kb + tg];
                a_h[mt][2] = wA[r * PADW + kb + 4 + tg];
                a_h[mt][3] = wA[(r + 8) * PADW + kb + 4 + tg];
                if (SPLIT) {
                    a_l[mt][0] = wL[r * PADW + kb + tg];
                    a_l[mt][1] = wL[(r + 8) * PADW + kb + tg];
                    a_l[mt][2] = wL[r * PADW + kb + 4 + tg];
                    a_l[mt][3] = wL[(r + 8) * PADW + kb + 4 + tg];
                }
            }
#pragma unroll
            for (int nt = 0; nt < 8; nt++) {
                int n = wn + nt * 8 + gp;
                b_h[nt][0] = wB[n * PADW + kb + tg];
                b_h[nt][1] = wB[n * PADW + kb + 4 + tg];
            }
#pragma unroll
            for (int mt = 0; mt < 2; mt++)
#pragma unroll
                for (int nt = 0; nt < 8; nt++) {
                    mma_f16(acc[mt][nt], a_h[mt], b_h[nt]);
                    if (SPLIT) mma_f16(acc[mt][nt], a_l[mt], b_h[nt]);
                }
        }
        __syncthreads();
        if (it + 2 < nIter) { LOAD_STAGE(it & 1, (it + 2) * 32) }
        else                { asm volatile("cp.async.commit_group;"); }
    }
#undef LOAD_STAGE

    if (mode == 1) {
        // smem-staged coalesced float4 store (N % 4 == 0)
        __syncthreads();
        float* so = (float*)sm8;   // 128 x 132 floats
#pragma unroll
        for (int mt = 0; mt < 2; mt++) {
            int r0 = wm + mt * 16 + gp;
#pragma unroll
            for (int nt = 0; nt < 8; nt++) {
                int cl = wn + nt * 8 + 2 * tg;
                so[r0 * 132 + cl]           = acc[mt][nt][0];
                so[r0 * 132 + cl + 1]       = acc[mt][nt][1];
                so[(r0 + 8) * 132 + cl]     = acc[mt][nt][2];
                so[(r0 + 8) * 132 + cl + 1] = acc[mt][nt][3];
            }
        }
        __syncthreads();
        int col = lane * 4;
        int cg = bn + col;
        if (cg < N) {
            for (int rr = warp; rr < 128; rr += 8) {
                int rg = bm + rr;
                float4 v = *(const float4*)&so[rr * 132 + col];
                *(float4*)&C[(size_t)rg * N + cg] = v;
            }
        }
    } else {
#pragma unroll
        for (int mt = 0; mt < 2; mt++) {
            int row0 = bm + wm + mt * 16 + gp;
#pragma unroll
            for (int nt = 0; nt < 8; nt++) {
                int col = bn + wn + nt * 8 + 2 * tg;
#pragma unroll
                for (int half = 0; half < 2; half++) {
                    int row = row0 + half * 8;
                    float* crow = C + (size_t)row * N;
#pragma unroll
                    for (int e = 0; e < 2; e++) {
                        int cc = col + e;
                        if (cc < N) {
                            float v = acc[mt][nt][half * 2 + e];
                            if (bias) v += bias[cc];
                            crow[cc] = v;
                        }
                    }
                }
            }
        }
    }
}

// ---------------- session boundaries ----------------
__global__ void k_bounds(const int* __restrict__ seg) {
    int t = blockIdx.x * blockDim.x + threadIdx.x;
    if (t >= TT) return;
    int s = seg[t];
    if (t == TT - 1 || seg[t + 1] != s) g_last[s]  = t;
    if (t == 0      || seg[t - 1] != s) g_start[s] = t;
}

// ------- lastE (half hi/lo): [et[i2x[last]], ft[c2x[last]]] -----------------
__global__ void k_lastE(const int* __restrict__ i2x, const int* __restrict__ c2x,
                        const float* __restrict__ et, const float* __restrict__ ft,
                        __half* __restrict__ lh, __half* __restrict__ ll) {
    int gid = blockIdx.x * blockDim.x + threadIdx.x;
    if (gid >= SS * D2) return;
    int s = gid >> 8;
    int d = gid & 255;
    int t = g_last[s];
    float x = (d < 128) ? et[(size_t)i2x[t] * DIM + d]
                        : ft[(size_t)c2x[t] * DIM + (d - 128)];
    __half hh = __float2half(x);
    lh[gid] = hh;
    ll[gid] = __float2half(x - __half2float(hh));
}

// --------- FMA-only sigmoid (no MUFU): exp2 poly + Newton reciprocal --------
__device__ __forceinline__ float fsig(float h) {
    float s = h * 1.44269504f;                       // h * log2(e)
    s = fminf(fmaxf(s, -126.f), 126.f);
    float n = floorf(s);
    float f = s - n;                                 // f in [0,1)
    // 2^f via degree-6 Taylor in ln2 (max rel err ~1.5e-5)
    float p = 1.5403530e-4f;
    p = fmaf(p, f, 1.3333558e-3f);
    p = fmaf(p, f, 9.6181291e-3f);
    p = fmaf(p, f, 5.5504109e-2f);
    p = fmaf(p, f, 2.4022651e-1f);
    p = fmaf(p, f, 6.9314718e-1f);
    p = fmaf(p, f, 1.0f);
    float r = __int_as_float(__float_as_int(p) + (((int)n) << 23));   // r = e^h
    float d = 1.f + r;
    float x = __int_as_float(0x7EF311C3 - __float_as_int(d));         // ~1/d
    x = x * (2.f - d * x);
    x = x * (2.f - d * x);
    x = x * (2.f - d * x);
    return r * x;                                    // r / (1 + r)
}

// ------ alpha[t] = q . sigmoid(Uet[i2x[t]] + Uft[c2x[t]] + Vs[seg[t]]) + qb --
__global__ void k_alpha(const float* __restrict__ Uet, const float* __restrict__ Uft,
                        const float* __restrict__ Vs,
                        const int* __restrict__ i2x, const int* __restrict__ c2x,
                        const int* __restrict__ seg, const float* __restrict__ qW,
                        const float* __restrict__ qb, float* __restrict__ alpha) {
    long gid = (long)blockIdx.x * blockDim.x + threadIdx.x;
    int t = (int)(gid >> 5);
    int lane = (int)(gid & 31);
    if (t >= TT) return;
    const float* u  = Uet + (size_t)i2x[t] * D2;
    const float* u2 = Uft + (size_t)c2x[t] * D2;
    const float* v  = Vs  + (size_t)seg[t] * D2;
    float sum = 0.f;
#pragma unroll
    for (int i = lane; i < D2; i += 32) {
        float h = u[i] + u2[i] + v[i];
        sum += qW[i] * fsig(h);
    }
#pragma unroll
    for (int o = 16; o; o >>= 1) sum += __shfl_xor_sync(0xFFFFFFFFu, sum, o);
    if (lane == 0) alpha[t] = sum + qb[0];
}

// ------ sg[s,d] (half) = sum_t alpha[t] * ([et[i2x[t]] | ft[c2x[t]]])[d] -----
__global__ void k_sg(const int* __restrict__ i2x, const int* __restrict__ c2x,
                     const float* __restrict__ et, const float* __restrict__ ft,
                     const float* __restrict__ alpha, __half* __restrict__ sgh) {
    int s = blockIdx.x;
    int d = threadIdx.x;  // 256
    float acc = 0.f;
    int st = g_start[s];
    if (st >= 0) {
        int en = g_last[s];
        if (d < 128) {
            for (int t = st; t <= en; ++t)
                acc += alpha[t] * et[(size_t)i2x[t] * DIM + d];
        } else {
            for (int t = st; t <= en; ++t)
                acc += alpha[t] * ft[(size_t)c2x[t] * DIM + (d - 128)];
        }
    }
    sgh[(size_t)s * D2 + d] = __float2half(acc);
}

// ============================ host launcher =================================
extern "C" void kernel_launch(void* const* d_in, const int* in_sizes, int n_in,
                              void* d_out, int out_size) {
    const int*   items    = (const int*)  d_in[0];
    const int*   cats     = (const int*)  d_in[1];
    const int*   item2idx = (const int*)  d_in[2];
    const int*   cat2idx  = (const int*)  d_in[3];
    const int*   item_e   = (const int*)  d_in[4];
    const int*   cat_e    = (const int*)  d_in[5];
    const float* item_ew  = (const float*)d_in[6];
    const float* cat_ew   = (const float*)d_in[7];
    const int*   seg      = (const int*)  d_in[8];
    const int*   cat4item = (const int*)  d_in[9];
    const float* item_tab = (const float*)d_in[10];
    const float* cat_tab  = (const float*)d_in[11];
    const float* iW  = (const float*)d_in[12];
    const float* ib  = (const float*)d_in[13];
    const float* cW  = (const float*)d_in[14];
    const float* cb  = (const float*)d_in[15];
    const float* w1W = (const float*)d_in[16];
    const float* w1b = (const float*)d_in[17];
    const float* w2W = (const float*)d_in[18];
    const float* qW  = (const float*)d_in[19];
    const float* qb  = (const float*)d_in[20];
    float* out = (float*)d_out;

    static float *p_iagg = nullptr, *p_cagg, *p_et, *p_ft, *p_Uet, *p_Uft,
                 *p_Vs, *p_alpha;
    static __half *p_iaggh, *p_iaggl, *p_caggh, *p_caggl, *p_eth, *p_etl,
                  *p_fth, *p_ftl, *p_lEh, *p_lEl, *p_sgh, *p_allh,
                  *p_iWh, *p_cWh, *p_w1Wh, *p_w2Wh;
    if (!p_iagg) {
        cudaGetSymbolAddress((void**)&p_iagg,  g_item_agg);
        cudaGetSymbolAddress((void**)&p_cagg,  g_cat_agg);
        cudaGetSymbolAddress((void**)&p_et,    g_et);
        cudaGetSymbolAddress((void**)&p_ft,    g_ft);
        cudaGetSymbolAddress((void**)&p_Uet,   g_Uet);
        cudaGetSymbolAddress((void**)&p_Uft,   g_Uft);
        cudaGetSymbolAddress((void**)&p_Vs,    g_Vs);
        cudaGetSymbolAddress((void**)&p_alpha, g_alpha);
        cudaGetSymbolAddress((void**)&p_iaggh, g_iaggh);
        cudaGetSymbolAddress((void**)&p_iaggl, g_iaggl);
        cudaGetSymbolAddress((void**)&p_caggh, g_caggh);
        cudaGetSymbolAddress((void**)&p_caggl, g_caggl);
        cudaGetSymbolAddress((void**)&p_eth,   g_eth);
        cudaGetSymbolAddress((void**)&p_etl,   g_etl);
        cudaGetSymbolAddress((void**)&p_fth,   g_fth);
        cudaGetSymbolAddress((void**)&p_ftl,   g_ftl);
        cudaGetSymbolAddress((void**)&p_lEh,   g_lastEh);
        cudaGetSymbolAddress((void**)&p_lEl,   g_lastEl);
        cudaGetSymbolAddress((void**)&p_sgh,   g_sgh);
        cudaGetSymbolAddress((void**)&p_allh,  g_allh);
        cudaGetSymbolAddress((void**)&p_iWh,   g_iWh);
        cudaGetSymbolAddress((void**)&p_cWh,   g_cWh);
        cudaGetSymbolAddress((void**)&p_w1Wh,  g_w1Wh);
        cudaGetSymbolAddress((void**)&p_w2Wh,  g_w2Wh);
        cudaFuncSetAttribute(k_hgemm<0>, cudaFuncAttributeMaxDynamicSharedMemorySize, 69632);
        cudaFuncSetAttribute(k_hgemm<1>, cudaFuncAttributeMaxDynamicSharedMemorySize, 69632);
    }
    const int SMF = 69632;   // max(2*2*10240, 128*132*4 = 67584)
    const int SMP = 61440;   // 2 stages * 3 tiles * 10240

    // 1. init + fused output table + weight conversions
    k_init<<<(NI * DIM + 255) / 256, 256>>>();
    k_fuse<<<(VV * D2 + 255) / 256, 256>>>(item_tab, cat_tab, cat4item, p_allh);
    k_cvt1h<<<(DIM * DIM + 255) / 256, 256>>>(iW,  p_iWh,  DIM * DIM);
    k_cvt1h<<<(DIM * DIM + 255) / 256, 256>>>(cW,  p_cWh,  DIM * DIM);
    k_cvt1h<<<(D2 * D2 + 255) / 256, 256>>>(w1W, p_w1Wh, D2 * D2);
    k_cvt1h<<<(D2 * D2 + 255) / 256, 256>>>(w2W, p_w2Wh, D2 * D2);

    // 2. edge scatters + split aggregates to half hi/lo
    k_edges<<<(EI * 32) / 256, 256>>>(item_e, item_ew, items, item_tab, p_iagg, EI);
    k_edges<<<(EC * 32) / 256, 256>>>(cat_e,  cat_ew,  cats,  cat_tab,  p_cagg, EC);
    k_split2h<<<(NI * DIM + 255) / 256, 256>>>(p_iagg, p_iaggh, p_iaggl, NI * DIM);
    k_split2h<<<(NC * DIM + 255) / 256, 256>>>(p_cagg, p_caggh, p_caggl, NC * DIM);

    // 3. node GNN linears (fp16 A-split)
    { dim3 g(1, NI / 128); k_hgemm<1><<<g, 256, SMP>>>(p_et, p_iaggh, p_iaggl, DIM, p_iWh, DIM, NI, DIM, DIM, ib, 0); }
    { dim3 g(1, NC / 128); k_hgemm<1><<<g, 256, SMP>>>(p_ft, p_caggh, p_caggl, DIM, p_cWh, DIM, NC, DIM, DIM, cb, 0); }
    k_split2h<<<(NI * DIM + 255) / 256, 256>>>(p_et, p_eth, p_etl, NI * DIM);
    k_split2h<<<(NC * DIM + 255) / 256, 256>>>(p_ft, p_fth, p_ftl, NC * DIM);

    // 4. U factorization at node level
    { dim3 g(2, NI / 128); k_hgemm<1><<<g, 256, SMP>>>(p_Uet, p_eth, p_etl, DIM, p_w1Wh,       D2, NI, D2, DIM, w1b,    0); }
    { dim3 g(2, NC / 128); k_hgemm<1><<<g, 256, SMP>>>(p_Uft, p_fth, p_ftl, DIM, p_w1Wh + DIM, D2, NC, D2, DIM, nullptr, 0); }

    // 5. session bounds + last embedding + Vs = lastE @ w2^T
    k_bounds<<<TT / 256, 256>>>(seg);
    k_lastE<<<(SS * D2 + 255) / 256, 256>>>(item2idx, cat2idx, p_et, p_ft, p_lEh, p_lEl);
    { dim3 g(2, SS / 128); k_hgemm<1><<<g, 256, SMP>>>(p_Vs, p_lEh, p_lEl, D2, p_w2Wh, D2, SS, D2, D2, nullptr, 0); }

    // 6. alpha (FMA-only sigmoid) + session aggregation
    k_alpha<<<(TT * 32) / 256, 256>>>(p_Uet, p_Uft, p_Vs, item2idx, cat2idx, seg, qW, qb, p_alpha);
    k_sg<<<SS, 256>>>(item2idx, cat2idx, p_et, p_ft, p_alpha, p_sgh);

    // 7. out = sg @ all_item^T   [S, V], K=256, staged coalesced stores
    { dim3 g((VV + 127) / 128, SS / 128);
      k_hgemm<0><<<g, 256, SMF>>>(out, p_sgh, nullptr, D2, p_allh, D2, SS, VV, D2, nullptr, 1); }
}

// round 13
// speedup vs baseline: 3.4874x; 1.0383x over previous
#include <cuda_runtime.h>
#include <cuda_fp16.h>
#include <stdint.h>
#include <math.h>

#define DIM   128
#define D2    256
#define NI    65536
#define NC    8192
#define EI    524288
#define EC    65536
#define TT    102400
#define SS    2048
#define VV    100000
#define NCAT  1000

// ---------------- scratch (device globals; no allocation allowed) -------------
__device__ float g_item_agg[NI * DIM];
__device__ float g_cat_agg [NC * DIM];
__device__ float g_et      [NI * DIM];
__device__ float g_ft      [NC * DIM];
__device__ float g_Uet     [NI * D2];
__device__ float g_Uft     [NC * D2];
__device__ float g_Vs      [SS * D2];
__device__ float g_alpha   [TT];
__device__ int   g_start   [SS];
__device__ int   g_last    [SS];
// half operands
__device__ __half g_iaggh[NI * DIM], g_iaggl[NI * DIM];
__device__ __half g_caggh[NC * DIM], g_caggl[NC * DIM];
__device__ __half g_eth  [NI * DIM], g_etl  [NI * DIM];
__device__ __half g_fth  [NC * DIM], g_ftl  [NC * DIM];
__device__ __half g_lastEh[SS * D2], g_lastEl[SS * D2];
__device__ __half g_sgh  [SS * D2];
__device__ __half g_allh [VV * D2];          // fused [item_tab | cat_tab[c4i]] half
__device__ __half g_iWh  [DIM * DIM], g_cWh[DIM * DIM];
__device__ __half g_w1Wh [D2 * D2],   g_w2Wh[D2 * D2];

// ---------------- init ----------------
__global__ void k_init() {
    int i = blockIdx.x * blockDim.x + threadIdx.x;
    if (i < NI * DIM) g_item_agg[i] = 0.f;
    if (i < NC * DIM) g_cat_agg[i]  = 0.f;
    if (i < SS) { g_start[i] = -1; g_last[i] = 0; }
}

// ---------------- conversions ----------------
__global__ void k_cvt1h(const float* __restrict__ src, __half* __restrict__ dst, int n) {
    int i = blockIdx.x * blockDim.x + threadIdx.x;
    if (i < n) dst[i] = __float2half(src[i]);
}
__global__ void k_split2h(const float* __restrict__ src, __half* __restrict__ h,
                          __half* __restrict__ l, int n) {
    int i = blockIdx.x * blockDim.x + threadIdx.x;
    if (i >= n) return;
    float x = src[i];
    __half hh = __float2half(x);
    h[i] = hh;
    l[i] = __float2half(x - __half2float(hh));
}
// fused table: all[v, 0:128] = item_tab[v], all[v, 128:256] = cat_tab[c4i[v]]
__global__ void k_fuse(const float* __restrict__ it, const float* __restrict__ ct,
                       const int* __restrict__ c4i, __half* __restrict__ all) {
    int i = blockIdx.x * blockDim.x + threadIdx.x;
    if (i >= VV * D2) return;
    int v = i >> 8, d = i & 255;
    float x = (d < 128) ? it[(size_t)v * DIM + d]
                        : ct[(size_t)c4i[v] * DIM + (d - 128)];
    all[i] = __float2half(x);
}

// ---------------- edge scatter ----------------
__global__ void k_edges(const int* __restrict__ edges, const float* __restrict__ ew,
                        const int* __restrict__ nodemap, const float* __restrict__ table,
                        float* __restrict__ agg, int E) {
    long gid = (long)blockIdx.x * blockDim.x + threadIdx.x;
    if (gid >= (long)E * 32) return;
    int e    = (int)(gid >> 5);
    int lane = (int)(gid & 31);
    int src = edges[e];
    int dst = edges[E + e];
    float w = ew[e];
    int id = nodemap[src];
    float4 v = *(const float4*)(table + (size_t)id * DIM + lane * 4);
    float* o = agg + (size_t)dst * DIM + lane * 4;
    asm volatile("red.global.add.v4.f32 [%0], {%1,%2,%3,%4};"
                 :: "l"(o), "f"(v.x * w), "f"(v.y * w), "f"(v.z * w), "f"(v.w * w)
                 : "memory");
}

// ---------------- fp16 mma + ldmatrix helpers ----------------
__device__ __forceinline__ void mma_f16(float c[4], const unsigned a[4], const unsigned b[2]) {
    asm volatile(
        "mma.sync.aligned.m16n8k16.row.col.f32.f16.f16.f32 "
        "{%0,%1,%2,%3}, {%4,%5,%6,%7}, {%8,%9}, {%0,%1,%2,%3};"
        : "+f"(c[0]), "+f"(c[1]), "+f"(c[2]), "+f"(c[3])
        : "r"(a[0]), "r"(a[1]), "r"(a[2]), "r"(a[3]), "r"(b[0]), "r"(b[1]));
}
__device__ __forceinline__ void ldsm_x4(unsigned r[4], uint32_t addr) {
    asm volatile("ldmatrix.sync.aligned.m8n8.x4.shared.b16 {%0,%1,%2,%3}, [%4];"
                 : "=r"(r[0]), "=r"(r[1]), "=r"(r[2]), "=r"(r[3]) : "r"(addr));
}

// ============ fp16 tensor GEMM: C[M,N] = A[M,K](lda) @ B[N,K]^T(ldb) =========
// SPLIT=1: A = Ah + Al (2 MMA chains). SPLIT=0: single.
// MODE 0: direct store (+bias), grid (n, m). MODE 1: smem-staged coalesced
//         float4 store, grid (m, n) so concurrent CTAs share B tiles in L2.
// BK=32. M%128==0, K%32==0. 2-stage cp.async double buffer, ldmatrix frags.
#define PADW  20
#define TILEB (128 * PADW * 4)
template<int SPLIT, int MODE>
__global__ __launch_bounds__(256, 2) void k_hgemm(
    float* __restrict__ C, const __half* __restrict__ Ah, const __half* __restrict__ Al,
    int lda, const __half* __restrict__ B, int ldb, int M, int N, int K,
    const float* __restrict__ bias) {
    constexpr int NTILE  = SPLIT ? 3 : 2;
    constexpr int STAGEB = NTILE * TILEB;
    extern __shared__ char sm8[];

    const int tid  = threadIdx.x;
    const int lane = tid & 31;
    const int warp = tid >> 5;
    const int wm = (warp >> 1) * 32;
    const int wn = (warp & 1) * 64;
    const int tg = lane & 3;
    const int gp = lane >> 2;
    const int bm = (MODE == 1 ? blockIdx.x : blockIdx.y) * 128;
    const int bn = (MODE == 1 ? blockIdx.y : blockIdx.x) * 128;
    const uint32_t sbase = (uint32_t)__cvta_generic_to_shared(sm8);

    // ldmatrix per-lane address components (bytes within a tile)
    const uint32_t aoff = (uint32_t)((wm + (lane & 15)) * (PADW * 4) + (lane >> 4) * 16);
    const uint32_t boff = (uint32_t)((wn + (lane & 7) + ((lane >> 4) << 3)) * (PADW * 4)
                                     + ((lane >> 3) & 1) * 16);

    float acc[2][8][4];
#pragma unroll
    for (int mt = 0; mt < 2; mt++)
#pragma unroll
        for (int nt = 0; nt < 8; nt++)
#pragma unroll
            for (int e = 0; e < 4; e++) acc[mt][nt][e] = 0.f;

    const int nIter = K / 32;

#define LOAD_STAGE(stage, k0)                                                           \
    {                                                                                   \
        const uint32_t so_ = sbase + (stage) * STAGEB;                                  \
        _Pragma("unroll")                                                               \
        for (int i_ = 0; i_ < 2; i_++) {                                                \
            int idx_ = i_ * 256 + tid;                                                  \
            int row_ = idx_ >> 2, c_ = idx_ & 3;                                        \
            uint32_t d_ = (uint32_t)(row_ * (PADW * 4) + c_ * 16);                      \
            const __half* pa_ = Ah + (size_t)(bm + row_) * lda + (k0) + c_ * 8;         \
            asm volatile("cp.async.cg.shared.global [%0], [%1], 16;"                    \
                         :: "r"(so_ + d_), "l"(pa_));                                   \
            if (SPLIT) {                                                                \
                const __half* pl_ = Al + (size_t)(bm + row_) * lda + (k0) + c_ * 8;     \
                asm volatile("cp.async.cg.shared.global [%0], [%1], 16;"                \
                             :: "r"(so_ + TILEB + d_), "l"(pl_));                       \
            }                                                                           \
            int rb_ = bn + row_; if (rb_ >= N) rb_ = N - 1;                             \
            const __half* pb_ = B + (size_t)rb_ * ldb + (k0) + c_ * 8;                  \
            asm volatile("cp.async.cg.shared.global [%0], [%1], 16;"                    \
                         :: "r"(so_ + (NTILE - 1) * TILEB + d_), "l"(pb_));             \
        }                                                                               \
        asm volatile("cp.async.commit_group;");                                        \
    }

    LOAD_STAGE(0, 0)
    if (nIter > 1) { LOAD_STAGE(1, 32) }
    else           { asm volatile("cp.async.commit_group;"); }

    for (int it = 0; it < nIter; ++it) {
        asm volatile("cp.async.wait_group 1;");
        __syncthreads();
        const uint32_t tA = sbase + (it & 1) * STAGEB;
        const uint32_t tL = tA + TILEB;
        const uint32_t tB = tA + (NTILE - 1) * TILEB;
#pragma unroll
        for (int kk = 0; kk < 2; kk++) {
            const uint32_t kboff = kk * 32;     // 8 words
            unsigned a_h[2][4], b_h[8][2];
            unsigned a_l[SPLIT ? 2 : 1][4];
#pragma unroll
            for (int mt = 0; mt < 2; mt++) {
                ldsm_x4(a_h[mt], tA + aoff + mt * (16 * PADW * 4) + kboff);
                if (SPLIT)
                    ldsm_x4(a_l[mt], tL + aoff + mt * (16 * PADW * 4) + kboff);
            }
#pragma unroll
            for (int p = 0; p < 4; p++) {
                unsigned bb[4];
                ldsm_x4(bb, tB + boff + p * (16 * PADW * 4) + kboff);
                b_h[2 * p][0]     = bb[0]; b_h[2 * p][1]     = bb[1];
                b_h[2 * p + 1][0] = bb[2]; b_h[2 * p + 1][1] = bb[3];
            }
#pragma unroll
            for (int mt = 0; mt < 2; mt++)
#pragma unroll
                for (int nt = 0; nt < 8; nt++) {
                    mma_f16(acc[mt][nt], a_h[mt], b_h[nt]);
                    if (SPLIT) mma_f16(acc[mt][nt], a_l[mt], b_h[nt]);
                }
        }
        __syncthreads();
        if (it + 2 < nIter) { LOAD_STAGE(it & 1, (it + 2) * 32) }
        else                { asm volatile("cp.async.commit_group;"); }
    }
#undef LOAD_STAGE

    if (MODE == 1) {
        // smem-staged coalesced float4 store (N % 4 == 0)
        __syncthreads();
        float* so = (float*)sm8;   // 128 x 132 floats
#pragma unroll
        for (int mt = 0; mt < 2; mt++) {
            int r0 = wm + mt * 16 + gp;
#pragma unroll
            for (int nt = 0; nt < 8; nt++) {
                int cl = wn + nt * 8 + 2 * tg;
                so[r0 * 132 + cl]           = acc[mt][nt][0];
                so[r0 * 132 + cl + 1]       = acc[mt][nt][1];
                so[(r0 + 8) * 132 + cl]     = acc[mt][nt][2];
                so[(r0 + 8) * 132 + cl + 1] = acc[mt][nt][3];
            }
        }
        __syncthreads();
        int col = lane * 4;
        int cg = bn + col;
        if (cg < N) {
            for (int rr = warp; rr < 128; rr += 8) {
                int rg = bm + rr;
                float4 v = *(const float4*)&so[rr * 132 + col];
                *(float4*)&C[(size_t)rg * N + cg] = v;
            }
        }
    } else {
#pragma unroll
        for (int mt = 0; mt < 2; mt++) {
            int row0 = bm + wm + mt * 16 + gp;
#pragma unroll
            for (int nt = 0; nt < 8; nt++) {
                int col = bn + wn + nt * 8 + 2 * tg;
#pragma unroll
                for (int half = 0; half < 2; half++) {
                    int row = row0 + half * 8;
                    float* crow = C + (size_t)row * N;
#pragma unroll
                    for (int e = 0; e < 2; e++) {
                        int cc = col + e;
                        if (cc < N) {
                            float v = acc[mt][nt][half * 2 + e];
                            if (bias) v += bias[cc];
                            crow[cc] = v;
                        }
                    }
                }
            }
        }
    }
}

// ---------------- session boundaries ----------------
__global__ void k_bounds(const int* __restrict__ seg) {
    int t = blockIdx.x * blockDim.x + threadIdx.x;
    if (t >= TT) return;
    int s = seg[t];
    if (t == TT - 1 || seg[t + 1] != s) g_last[s]  = t;
    if (t == 0      || seg[t - 1] != s) g_start[s] = t;
}

// ------- lastE (half hi/lo): [et[i2x[last]], ft[c2x[last]]] -----------------
__global__ void k_lastE(const int* __restrict__ i2x, const int* __restrict__ c2x,
                        const float* __restrict__ et, const float* __restrict__ ft,
                        __half* __restrict__ lh, __half* __restrict__ ll) {
    int gid = blockIdx.x * blockDim.x + threadIdx.x;
    if (gid >= SS * D2) return;
    int s = gid >> 8;
    int d = gid & 255;
    int t = g_last[s];
    float x = (d < 128) ? et[(size_t)i2x[t] * DIM + d]
                        : ft[(size_t)c2x[t] * DIM + (d - 128)];
    __half hh = __float2half(x);
    lh[gid] = hh;
    ll[gid] = __float2half(x - __half2float(hh));
}

// --------- FMA-only sigmoid (no MUFU): exp2 poly + Newton reciprocal --------
__device__ __forceinline__ float fsig(float h) {
    float s = h * 1.44269504f;                       // h * log2(e)
    s = fminf(fmaxf(s, -126.f), 126.f);
    float n = floorf(s);
    float f = s - n;                                 // f in [0,1)
    float p = 1.5403530e-4f;
    p = fmaf(p, f, 1.3333558e-3f);
    p = fmaf(p, f, 9.6181291e-3f);
    p = fmaf(p, f, 5.5504109e-2f);
    p = fmaf(p, f, 2.4022651e-1f);
    p = fmaf(p, f, 6.9314718e-1f);
    p = fmaf(p, f, 1.0f);
    float r = __int_as_float(__float_as_int(p) + (((int)n) << 23));   // e^h
    float d = 1.f + r;
    float x = __int_as_float(0x7EF311C3 - __float_as_int(d));
    x = x * (2.f - d * x);
    x = x * (2.f - d * x);
    x = x * (2.f - d * x);
    return r * x;
}

// ------ alpha[t] = q . sigmoid(Uet[i2x[t]] + Uft[c2x[t]] + Vs[seg[t]]) + qb --
__global__ void k_alpha(const float* __restrict__ Uet, const float* __restrict__ Uft,
                        const float* __restrict__ Vs,
                        const int* __restrict__ i2x, const int* __restrict__ c2x,
                        const int* __restrict__ seg, const float* __restrict__ qW,
                        const float* __restrict__ qb, float* __restrict__ alpha) {
    long gid = (long)blockIdx.x * blockDim.x + threadIdx.x;
    int t = (int)(gid >> 5);
    int lane = (int)(gid & 31);
    if (t >= TT) return;
    const float* u  = Uet + (size_t)i2x[t] * D2;
    const float* u2 = Uft + (size_t)c2x[t] * D2;
    const float* v  = Vs  + (size_t)seg[t] * D2;
    float sum = 0.f;
#pragma unroll
    for (int i = lane; i < D2; i += 32) {
        float h = u[i] + u2[i] + v[i];
        sum += qW[i] * fsig(h);
    }
#pragma unroll
    for (int o = 16; o; o >>= 1) sum += __shfl_xor_sync(0xFFFFFFFFu, sum, o);
    if (lane == 0) alpha[t] = sum + qb[0];
}

// ------ sg[s,d] (half) = sum_t alpha[t] * ([et[i2x[t]] | ft[c2x[t]]])[d] -----
__global__ void k_sg(const int* __restrict__ i2x, const int* __restrict__ c2x,
                     const float* __restrict__ et, const float* __restrict__ ft,
                     const float* __restrict__ alpha, __half* __restrict__ sgh) {
    int s = blockIdx.x;
    int d = threadIdx.x;  // 256
    float acc = 0.f;
    int st = g_start[s];
    if (st >= 0) {
        int en = g_last[s];
        if (d < 128) {
            for (int t = st; t <= en; ++t)
                acc += alpha[t] * et[(size_t)i2x[t] * DIM + d];
        } else {
            for (int t = st; t <= en; ++t)
                acc += alpha[t] * ft[(size_t)c2x[t] * DIM + (d - 128)];
        }
    }
    sgh[(size_t)s * D2 + d] = __float2half(acc);
}

// ============================ host launcher =================================
extern "C" void kernel_launch(void* const* d_in, const int* in_sizes, int n_in,
                              void* d_out, int out_size) {
    const int*   items    = (const int*)  d_in[0];
    const int*   cats     = (const int*)  d_in[1];
    const int*   item2idx = (const int*)  d_in[2];
    const int*   cat2idx  = (const int*)  d_in[3];
    const int*   item_e   = (const int*)  d_in[4];
    const int*   cat_e    = (const int*)  d_in[5];
    const float* item_ew  = (const float*)d_in[6];
    const float* cat_ew   = (const float*)d_in[7];
    const int*   seg      = (const int*)  d_in[8];
    const int*   cat4item = (const int*)  d_in[9];
    const float* item_tab = (const float*)d_in[10];
    const float* cat_tab  = (const float*)d_in[11];
    const float* iW  = (const float*)d_in[12];
    const float* ib  = (const float*)d_in[13];
    const float* cW  = (const float*)d_in[14];
    const float* cb  = (const float*)d_in[15];
    const float* w1W = (const float*)d_in[16];
    const float* w1b = (const float*)d_in[17];
    const float* w2W = (const float*)d_in[18];
    const float* qW  = (const float*)d_in[19];
    const float* qb  = (const float*)d_in[20];
    float* out = (float*)d_out;

    static float *p_iagg = nullptr, *p_cagg, *p_et, *p_ft, *p_Uet, *p_Uft,
                 *p_Vs, *p_alpha;
    static __half *p_iaggh, *p_iaggl, *p_caggh, *p_caggl, *p_eth, *p_etl,
                  *p_fth, *p_ftl, *p_lEh, *p_lEl, *p_sgh, *p_allh,
                  *p_iWh, *p_cWh, *p_w1Wh, *p_w2Wh;
    if (!p_iagg) {
        cudaGetSymbolAddress((void**)&p_iagg,  g_item_agg);
        cudaGetSymbolAddress((void**)&p_cagg,  g_cat_agg);
        cudaGetSymbolAddress((void**)&p_et,    g_et);
        cudaGetSymbolAddress((void**)&p_ft,    g_ft);
        cudaGetSymbolAddress((void**)&p_Uet,   g_Uet);
        cudaGetSymbolAddress((void**)&p_Uft,   g_Uft);
        cudaGetSymbolAddress((void**)&p_Vs,    g_Vs);
        cudaGetSymbolAddress((void**)&p_alpha, g_alpha);
        cudaGetSymbolAddress((void**)&p_iaggh, g_iaggh);
        cudaGetSymbolAddress((void**)&p_iaggl, g_iaggl);
        cudaGetSymbolAddress((void**)&p_caggh, g_caggh);
        cudaGetSymbolAddress((void**)&p_caggl, g_caggl);
        cudaGetSymbolAddress((void**)&p_eth,   g_eth);
        cudaGetSymbolAddress((void**)&p_etl,   g_etl);
        cudaGetSymbolAddress((void**)&p_fth,   g_fth);
        cudaGetSymbolAddress((void**)&p_ftl,   g_ftl);
        cudaGetSymbolAddress((void**)&p_lEh,   g_lastEh);
        cudaGetSymbolAddress((void**)&p_lEl,   g_lastEl);
        cudaGetSymbolAddress((void**)&p_sgh,   g_sgh);
        cudaGetSymbolAddress((void**)&p_allh,  g_allh);
        cudaGetSymbolAddress((void**)&p_iWh,   g_iWh);
        cudaGetSymbolAddress((void**)&p_cWh,   g_cWh);
        cudaGetSymbolAddress((void**)&p_w1Wh,  g_w1Wh);
        cudaGetSymbolAddress((void**)&p_w2Wh,  g_w2Wh);
        cudaFuncSetAttribute((const void*)k_hgemm<1,0>, cudaFuncAttributeMaxDynamicSharedMemorySize, 69632);
        cudaFuncSetAttribute((const void*)k_hgemm<0,1>, cudaFuncAttributeMaxDynamicSharedMemorySize, 69632);
    }
    const int SMF = 69632;   // max(2*2*10240, 128*132*4 = 67584)
    const int SMP = 61440;   // 2 stages * 3 tiles * 10240

    // 1. init + fused output table + weight conversions
    k_init<<<(NI * DIM + 255) / 256, 256>>>();
    k_fuse<<<(VV * D2 + 255) / 256, 256>>>(item_tab, cat_tab, cat4item, p_allh);
    k_cvt1h<<<(DIM * DIM + 255) / 256, 256>>>(iW,  p_iWh,  DIM * DIM);
    k_cvt1h<<<(DIM * DIM + 255) / 256, 256>>>(cW,  p_cWh,  DIM * DIM);
    k_cvt1h<<<(D2 * D2 + 255) / 256, 256>>>(w1W, p_w1Wh, D2 * D2);
    k_cvt1h<<<(D2 * D2 + 255) / 256, 256>>>(w2W, p_w2Wh, D2 * D2);

    // 2. edge scatters + split aggregates to half hi/lo
    k_edges<<<(EI * 32) / 256, 256>>>(item_e, item_ew, items, item_tab, p_iagg, EI);
    k_edges<<<(EC * 32) / 256, 256>>>(cat_e,  cat_ew,  cats,  cat_tab,  p_cagg, EC);
    k_split2h<<<(NI * DIM + 255) / 256, 256>>>(p_iagg, p_iaggh, p_iaggl, NI * DIM);
    k_split2h<<<(NC * DIM + 255) / 256, 256>>>(p_cagg, p_caggh, p_caggl, NC * DIM);

    // 3. node GNN linears (fp16 A-split)
    { dim3 g(1, NI / 128); k_hgemm<1,0><<<g, 256, SMP>>>(p_et, p_iaggh, p_iaggl, DIM, p_iWh, DIM, NI, DIM, DIM, ib); }
    { dim3 g(1, NC / 128); k_hgemm<1,0><<<g, 256, SMP>>>(p_ft, p_caggh, p_caggl, DIM, p_cWh, DIM, NC, DIM, DIM, cb); }
    k_split2h<<<(NI * DIM + 255) / 256, 256>>>(p_et, p_eth, p_etl, NI * DIM);
    k_split2h<<<(NC * DIM + 255) / 256, 256>>>(p_ft, p_fth, p_ftl, NC * DIM);

    // 4. U factorization at node level
    { dim3 g(2, NI / 128); k_hgemm<1,0><<<g, 256, SMP>>>(p_Uet, p_eth, p_etl, DIM, p_w1Wh,       D2, NI, D2, DIM, w1b); }
    { dim3 g(2, NC / 128); k_hgemm<1,0><<<g, 256, SMP>>>(p_Uft, p_fth, p_ftl, DIM, p_w1Wh + DIM, D2, NC, D2, DIM, nullptr); }

    // 5. session bounds + last embedding + Vs = lastE @ w2^T
    k_bounds<<<TT / 256, 256>>>(seg);
    k_lastE<<<(SS * D2 + 255) / 256, 256>>>(item2idx, cat2idx, p_et, p_ft, p_lEh, p_lEl);
    { dim3 g(2, SS / 128); k_hgemm<1,0><<<g, 256, SMP>>>(p_Vs, p_lEh, p_lEl, D2, p_w2Wh, D2, SS, D2, D2, nullptr); }

    // 6. alpha (FMA-only sigmoid) + session aggregation
    k_alpha<<<(TT * 32) / 256, 256>>>(p_Uet, p_Uft, p_Vs, item2idx, cat2idx, seg, qW, qb, p_alpha);
    k_sg<<<SS, 256>>>(item2idx, cat2idx, p_et, p_ft, p_alpha, p_sgh);

    // 7. out = sg @ all_item^T  [S, V], K=256 — grid (m, n) for B L2 reuse
    { dim3 g(SS / 128, (VV + 127) / 128);
      k_hgemm<0,1><<<g, 256, SMF>>>(out, p_sgh, nullptr, D2, p_allh, D2, SS, VV, D2, nullptr); }
}